// round 1
// baseline (speedup 1.0000x reference)
#include <cuda_runtime.h>
#include <math.h>

#define BATCH 4
#define SEQ_N 1024
#define SEQ_K 1024
#define DIMF  2048
#define NHEAD 16
#define DHEAD 64
#define ROUTES 2
#define HPR   (NHEAD/ROUTES)
#define DHID  (NHEAD*DHEAD)   // 1024

// ---------------- scratch (static device allocations) ----------------
__device__ float g_xn[(size_t)BATCH*SEQ_N*DIMF];           // normed x        (4096, 2048)
__device__ float g_cn[(size_t)BATCH*ROUTES*SEQ_K*DIMF];    // normed context  (8192, 2048)
__device__ float g_q [(size_t)BATCH*NHEAD*SEQ_N*DHEAD];    // (b,h,n,d)  pre-scaled by score_q * 1/sqrt(d)
__device__ float g_k [(size_t)BATCH*NHEAD*SEQ_K*DHEAD];    // (b,h,nk,d) pre-scaled by score_kv
__device__ float g_v [(size_t)BATCH*NHEAD*SEQ_K*DHEAD];    // (b,h,nk,d) pre-scaled by score_kv
__device__ float g_ao[(size_t)BATCH*SEQ_N*DHID];           // attention out (b,n,h*d)

// ---------------- RMS norm ----------------
// one block (256 threads) per row of 2048 floats
__global__ void __launch_bounds__(256) rmsnorm_kernel(
    const float* __restrict__ in, const float* __restrict__ gamma,
    float* __restrict__ out)
{
    const long row = blockIdx.x;
    const float4* xr = (const float4*)(in + row * (long)DIMF);
    float4*       orow = (float4*)(out + row * (long)DIMF);
    const float4* g4 = (const float4*)gamma;
    const int t = threadIdx.x;

    float4 v0 = xr[t];
    float4 v1 = xr[t + 256];
    float ss = v0.x*v0.x + v0.y*v0.y + v0.z*v0.z + v0.w*v0.w
             + v1.x*v1.x + v1.y*v1.y + v1.z*v1.z + v1.w*v1.w;
    #pragma unroll
    for (int o = 16; o; o >>= 1) ss += __shfl_xor_sync(0xffffffffu, ss, o);
    __shared__ float red[8];
    if ((t & 31) == 0) red[t >> 5] = ss;
    __syncthreads();
    float tot = 0.f;
    #pragma unroll
    for (int i = 0; i < 8; i++) tot += red[i];
    const float s = sqrtf((float)DIMF) / fmaxf(sqrtf(tot), 1e-12f);

    float4 ga = g4[t], gb = g4[t + 256];
    orow[t]       = make_float4(v0.x*s*ga.x, v0.y*s*ga.y, v0.z*s*ga.z, v0.w*s*ga.w);
    orow[t + 256] = make_float4(v1.x*s*gb.x, v1.y*s*gb.y, v1.z*s*gb.z, v1.w*s*gb.w);
}

// ---------------- tiled SGEMM, C(M,N) = A(M,K) * B(N,K)^T ----------------
// 128x128 tile, BK=16, 256 threads, 8x8 per thread. Epilogue by MODE.
// MODE 0: Q proj   (A=g_xn, B=Wq,  K=2048)  -> g_q, scaled by score_q * 0.125
// MODE 1: KV proj  (A=g_cn[z], B=Wkv[route], K=2048) -> g_k/g_v, scaled by score_kv
// MODE 2: O proj   (A=g_ao, B=Wo,  K=1024)  -> d_out
template <int MODE>
__global__ void __launch_bounds__(256) gemm128(
    const float* __restrict__ Bw,
    const float* __restrict__ sc,
    float* __restrict__ out)
{
    constexpr int K = (MODE == 2) ? DHID : DIMF;
    const int bm = blockIdx.y, bn = blockIdx.x, bz = blockIdx.z;

    const float* A;
    const float* Bp;
    if (MODE == 0)      { A = g_xn + (long)bm * 128 * K;                         Bp = Bw; }
    else if (MODE == 1) { A = g_cn + ((long)bz * SEQ_K + (long)bm * 128) * K;    Bp = Bw + (long)(bz % ROUTES) * DHID * K; }
    else                { A = g_ao + (long)bm * 128 * K;                         Bp = Bw; }
    Bp += (long)bn * 128 * K;

    __shared__ float As[16][128];
    __shared__ float Bs[16][128];

    const int tid = threadIdx.x;
    const int tx = tid & 15, ty = tid >> 4;

    float acc[8][8];
    #pragma unroll
    for (int i = 0; i < 8; i++)
        #pragma unroll
        for (int j = 0; j < 8; j++) acc[i][j] = 0.f;

    for (int k0 = 0; k0 < K; k0 += 16) {
        #pragma unroll
        for (int i = 0; i < 2; i++) {
            int idx = tid + i * 256;          // 512 float4 per tile
            int rr = idx >> 2, kc = (idx & 3) << 2;
            float4 av = *(const float4*)(A  + (long)rr * K + k0 + kc);
            As[kc+0][rr] = av.x; As[kc+1][rr] = av.y; As[kc+2][rr] = av.z; As[kc+3][rr] = av.w;
            float4 bv = *(const float4*)(Bp + (long)rr * K + k0 + kc);
            Bs[kc+0][rr] = bv.x; Bs[kc+1][rr] = bv.y; Bs[kc+2][rr] = bv.z; Bs[kc+3][rr] = bv.w;
        }
        __syncthreads();
        #pragma unroll
        for (int kk = 0; kk < 16; kk++) {
            float a[8], b[8];
            *(float4*)(a)     = *(const float4*)&As[kk][ty * 8];
            *(float4*)(a + 4) = *(const float4*)&As[kk][ty * 8 + 4];
            *(float4*)(b)     = *(const float4*)&Bs[kk][tx * 8];
            *(float4*)(b + 4) = *(const float4*)&Bs[kk][tx * 8 + 4];
            #pragma unroll
            for (int i = 0; i < 8; i++)
                #pragma unroll
                for (int j = 0; j < 8; j++)
                    acc[i][j] = fmaf(a[i], b[j], acc[i][j]);
        }
        __syncthreads();
    }

    #pragma unroll
    for (int i = 0; i < 8; i++) {
        const int m = bm * 128 + ty * 8 + i;
        #pragma unroll
        for (int j = 0; j < 8; j++) {
            const int o = bn * 128 + tx * 8 + j;
            float v = acc[i][j];
            if (MODE == 0) {
                // m in [0,4096): b*1024+n ; o in [0,1024): h*64+d
                int b = m >> 10, nn = m & 1023;
                int h = o >> 6,  d  = o & 63;
                g_q[(((long)(b * NHEAD + h)) * SEQ_N + nn) * DHEAD + d] =
                    v * sc[m] * 0.125f;                        // fold 1/sqrt(64)
            } else if (MODE == 1) {
                // bz = b*ROUTES + r ; m = nk index ; o = h'*128 + dd
                int hp = o >> 7, dd = o & 127;
                int b = bz / ROUTES, rt = bz % ROUTES;
                float s = sc[(long)bz * SEQ_K + m];
                long base = (((long)(b * NHEAD + rt * HPR + hp)) * SEQ_K + m) * DHEAD;
                if (dd < DHEAD) g_k[base + dd]          = v * s;
                else            g_v[base + dd - DHEAD]  = v * s;
            } else {
                out[(long)m * DIMF + o] = v;
            }
        }
    }
}

// ---------------- flash attention (fp32, single pass) ----------------
// grid: (SEQ_N/32, BATCH*NHEAD). 256 threads = 8 warps, 4 query rows per warp.
// Keys: null key first, then 16 tiles of 64. K and V share one smem buffer.
__global__ void __launch_bounds__(256) attn_kernel(const float* __restrict__ nullkv)
{
    const int bh    = blockIdx.y;
    const int h     = bh & (NHEAD - 1);
    const int qbase = blockIdx.x * 32;
    const int tid = threadIdx.x, lane = tid & 31, w = tid >> 5;

    __shared__ float KVs[64][65];     // K tile, then reused for V tile
    __shared__ float qs[32][64];
    __shared__ float ps[32][64];
    __shared__ float nk_s[64], nv_s[64];

    // load 32 q rows (already scaled by score_q * 1/sqrt(d))
    const float* qg = g_q + ((long)bh * SEQ_N + qbase) * DHEAD;
    #pragma unroll
    for (int i = 0; i < 2; i++) {
        int idx = tid + i * 256;                 // 512 float4
        int r = idx >> 4, c = (idx & 15) << 2;
        float4 v = *(const float4*)(qg + (long)r * DHEAD + c);
        qs[r][c] = v.x; qs[r][c+1] = v.y; qs[r][c+2] = v.z; qs[r][c+3] = v.w;
    }
    if (tid < 64)       nk_s[tid]      = nullkv[h * DHEAD + tid];
    else if (tid < 128) nv_s[tid - 64] = nullkv[NHEAD * DHEAD + h * DHEAD + (tid - 64)];
    __syncthreads();

    // init online softmax with the null key (index 0): m=s0, l=1, o=nullv
    float m[4], l[4], o0[4], o1[4];
    #pragma unroll
    for (int rr = 0; rr < 4; rr++) {
        int row = w * 4 + rr;
        float p = qs[row][lane] * nk_s[lane] + qs[row][lane + 32] * nk_s[lane + 32];
        #pragma unroll
        for (int off = 16; off; off >>= 1) p += __shfl_xor_sync(0xffffffffu, p, off);
        m[rr] = p; l[rr] = 1.f;
        o0[rr] = nv_s[lane]; o1[rr] = nv_s[lane + 32];
    }

    const float* kg = g_k + (long)bh * SEQ_K * DHEAD;
    const float* vg = g_v + (long)bh * SEQ_K * DHEAD;

    for (int t = 0; t < 16; t++) {
        __syncthreads();   // previous accumulate done before overwriting KVs
        #pragma unroll
        for (int i = 0; i < 4; i++) {
            int idx = tid + i * 256;             // 1024 float4
            int r = idx >> 4, c = (idx & 15) << 2;
            float4 kv4 = *(const float4*)(kg + (long)(t * 64 + r) * DHEAD + c);
            KVs[r][c] = kv4.x; KVs[r][c+1] = kv4.y; KVs[r][c+2] = kv4.z; KVs[r][c+3] = kv4.w;
        }
        __syncthreads();

        // scores: lane handles keys j=lane and j=lane+32 for 4 rows
        float sa[4] = {0,0,0,0}, sb[4] = {0,0,0,0};
        #pragma unroll
        for (int d = 0; d < 64; d++) {
            float ka = KVs[lane][d], kb = KVs[lane + 32][d];
            #pragma unroll
            for (int rr = 0; rr < 4; rr++) {
                float qv = qs[w * 4 + rr][d];
                sa[rr] = fmaf(qv, ka, sa[rr]);
                sb[rr] = fmaf(qv, kb, sb[rr]);
            }
        }

        // online softmax update per row
        #pragma unroll
        for (int rr = 0; rr < 4; rr++) {
            float mt = fmaxf(sa[rr], sb[rr]);
            #pragma unroll
            for (int off = 16; off; off >>= 1)
                mt = fmaxf(mt, __shfl_xor_sync(0xffffffffu, mt, off));
            float mn   = fmaxf(m[rr], mt);
            float corr = __expf(m[rr] - mn);
            float pa   = __expf(sa[rr] - mn);
            float pb   = __expf(sb[rr] - mn);
            float psum = pa + pb;
            #pragma unroll
            for (int off = 16; off; off >>= 1)
                psum += __shfl_xor_sync(0xffffffffu, psum, off);
            l[rr] = l[rr] * corr + psum;
            o0[rr] *= corr; o1[rr] *= corr;
            m[rr] = mn;
            ps[w * 4 + rr][lane]      = pa;
            ps[w * 4 + rr][lane + 32] = pb;
        }
        __syncwarp();

        __syncthreads();   // all warps done reading K tile
        #pragma unroll
        for (int i = 0; i < 4; i++) {
            int idx = tid + i * 256;
            int r = idx >> 4, c = (idx & 15) << 2;
            float4 vv4 = *(const float4*)(vg + (long)(t * 64 + r) * DHEAD + c);
            KVs[r][c] = vv4.x; KVs[r][c+1] = vv4.y; KVs[r][c+2] = vv4.z; KVs[r][c+3] = vv4.w;
        }
        __syncthreads();

        #pragma unroll 8
        for (int j = 0; j < 64; j++) {
            float v0 = KVs[j][lane], v1 = KVs[j][lane + 32];
            #pragma unroll
            for (int rr = 0; rr < 4; rr++) {
                float p = ps[w * 4 + rr][j];
                o0[rr] = fmaf(p, v0, o0[rr]);
                o1[rr] = fmaf(p, v1, o1[rr]);
            }
        }
    }

    // write (b, n, h*64+d)
    const int b = bh >> 4;
    #pragma unroll
    for (int rr = 0; rr < 4; rr++) {
        int n = qbase + w * 4 + rr;
        float inv = 1.f / l[rr];
        long base = ((long)(b * SEQ_N + n)) * DHID + h * DHEAD;
        g_ao[base + lane]      = o0[rr] * inv;
        g_ao[base + lane + 32] = o1[rr] * inv;
    }
}

// ---------------- launch ----------------
extern "C" void kernel_launch(void* const* d_in, const int* in_sizes, int n_in,
                              void* d_out, int out_size)
{
    const float* x      = (const float*)d_in[0];
    const float* ctx    = (const float*)d_in[1];
    const float* skv    = (const float*)d_in[2];
    const float* sq     = (const float*)d_in[3];
    const float* gamma  = (const float*)d_in[4];
    const float* nullkv = (const float*)d_in[5];
    const float* Wq     = (const float*)d_in[6];
    const float* Wkv    = (const float*)d_in[7];
    const float* Wo     = (const float*)d_in[8];
    float* out = (float*)d_out;

    float* xn; cudaGetSymbolAddress((void**)&xn, g_xn);
    float* cn; cudaGetSymbolAddress((void**)&cn, g_cn);

    rmsnorm_kernel<<<BATCH * SEQ_N, 256>>>(x, gamma, xn);
    rmsnorm_kernel<<<BATCH * ROUTES * SEQ_K, 256>>>(ctx, gamma, cn);

    // Q projection: (4096 x 1024 x 2048)
    gemm128<0><<<dim3(DHID / 128, (BATCH * SEQ_N) / 128, 1), 256>>>(Wq, sq, nullptr);
    // KV projection: 8 x (1024 x 1024 x 2048)
    gemm128<1><<<dim3(DHID / 128, SEQ_K / 128, BATCH * ROUTES), 256>>>(Wkv, skv, nullptr);
    // attention
    attn_kernel<<<dim3(SEQ_N / 32, BATCH * NHEAD), 256>>>(nullkv);
    // output projection: (4096 x 2048 x 1024)
    gemm128<2><<<dim3(DIMF / 128, (BATCH * SEQ_N) / 128, 1), 256>>>(Wo, nullptr, out);
}

// round 2
// speedup vs baseline: 2.2173x; 2.2173x over previous
#include <cuda_runtime.h>
#include <math.h>
#include <stdint.h>

#define BATCH 4
#define SEQ_N 1024
#define SEQ_K 1024
#define DIMF  2048
#define NHEAD 16
#define DHEAD 64
#define ROUTES 2
#define HPR   (NHEAD/ROUTES)
#define DHID  (NHEAD*DHEAD)   // 1024

// ---------------- scratch (static device allocations) ----------------
__device__ float g_xn[(size_t)BATCH*SEQ_N*DIMF];           // normed x, tf32-rounded
__device__ float g_cn[(size_t)BATCH*ROUTES*SEQ_K*DIMF];    // normed context, tf32-rounded
__device__ float g_q [(size_t)BATCH*NHEAD*SEQ_N*DHEAD];    // (b,h,n,d)  scaled by score_q/8
__device__ float g_k [(size_t)BATCH*NHEAD*SEQ_K*DHEAD];    // (b,h,nk,d) scaled by score_kv
__device__ float g_v [(size_t)BATCH*NHEAD*SEQ_K*DHEAD];
__device__ float g_ao[(size_t)BATCH*SEQ_N*DHID];           // attn out, tf32-rounded
__device__ float g_wq [(size_t)DHID*DIMF];                 // tf32-rounded weights
__device__ float g_wkv[(size_t)2*DHID*DIMF];
__device__ float g_wo [(size_t)DIMF*DHID];

// ---------------- helpers ----------------
__device__ __forceinline__ float tf32r(float x) {
    uint32_t u; asm("cvt.rna.tf32.f32 %0, %1;" : "=r"(u) : "f"(x));
    return __uint_as_float(u);
}
__device__ __forceinline__ void cp16(void* dst_smem, const void* src) {
    uint32_t d = (uint32_t)__cvta_generic_to_shared(dst_smem);
    asm volatile("cp.async.cg.shared.global [%0], [%1], 16;" :: "r"(d), "l"(src));
}
__device__ __forceinline__ void mma8(float* c, const uint32_t* a, const uint32_t* b) {
    asm volatile("mma.sync.aligned.m16n8k8.row.col.f32.tf32.tf32.f32 "
        "{%0,%1,%2,%3},{%4,%5,%6,%7},{%8,%9},{%0,%1,%2,%3};"
        : "+f"(c[0]), "+f"(c[1]), "+f"(c[2]), "+f"(c[3])
        : "r"(a[0]), "r"(a[1]), "r"(a[2]), "r"(a[3]), "r"(b[0]), "r"(b[1]));
}

// ---------------- tf32 rounding prep (weights) ----------------
__global__ void __launch_bounds__(256) round_tf32_kernel(
    const float4* __restrict__ in, float4* __restrict__ out, int n4)
{
    int i = blockIdx.x * 256 + threadIdx.x;
    if (i < n4) {
        float4 v = in[i];
        v.x = tf32r(v.x); v.y = tf32r(v.y); v.z = tf32r(v.z); v.w = tf32r(v.w);
        out[i] = v;
    }
}

// ---------------- RMS norm (tf32-rounded output) ----------------
__global__ void __launch_bounds__(256) rmsnorm_kernel(
    const float* __restrict__ in, const float* __restrict__ gamma,
    float* __restrict__ out)
{
    const long row = blockIdx.x;
    const float4* xr = (const float4*)(in + row * (long)DIMF);
    float4*       orow = (float4*)(out + row * (long)DIMF);
    const float4* g4 = (const float4*)gamma;
    const int t = threadIdx.x;

    float4 v0 = xr[t];
    float4 v1 = xr[t + 256];
    float ss = v0.x*v0.x + v0.y*v0.y + v0.z*v0.z + v0.w*v0.w
             + v1.x*v1.x + v1.y*v1.y + v1.z*v1.z + v1.w*v1.w;
    #pragma unroll
    for (int o = 16; o; o >>= 1) ss += __shfl_xor_sync(0xffffffffu, ss, o);
    __shared__ float red[8];
    if ((t & 31) == 0) red[t >> 5] = ss;
    __syncthreads();
    float tot = 0.f;
    #pragma unroll
    for (int i = 0; i < 8; i++) tot += red[i];
    const float s = sqrtf((float)DIMF) / fmaxf(sqrtf(tot), 1e-12f);

    float4 ga = g4[t], gb = g4[t + 256];
    orow[t]       = make_float4(tf32r(v0.x*s*ga.x), tf32r(v0.y*s*ga.y),
                                tf32r(v0.z*s*ga.z), tf32r(v0.w*s*ga.w));
    orow[t + 256] = make_float4(tf32r(v1.x*s*gb.x), tf32r(v1.y*s*gb.y),
                                tf32r(v1.z*s*gb.z), tf32r(v1.w*s*gb.w));
}

// ---------------- tf32 tensor-core GEMM, C(M,N) = A(M,K) * B(N,K)^T ----------------
// 128x128 tile, BK=16, 256 threads (8 warps as 2x4), warp tile 64x32.
// smem layout: K-inner, row stride 16, per-row XOR swizzle of 4-float groups:
//   pos(row, k) = row*16 + (k ^ (((row>>1)&3)<<2))    -> conflict-free frag LDS
// 3-stage cp.async pipeline (exactly 48KB static smem).
// MODE 0: Q proj  (A=g_xn, B=g_wq,  K=2048) -> g_q  scaled score_q*0.125
// MODE 1: KV proj (A=g_cn, B=g_wkv, K=2048) -> g_k/g_v scaled score_kv
// MODE 2: O proj  (A=g_ao, B=g_wo,  K=1024) -> d_out
template <int MODE>
__global__ void __launch_bounds__(256) gemm_tc(
    const float* __restrict__ sc, float* __restrict__ out)
{
    constexpr int K  = (MODE == 2) ? DHID : DIMF;
    constexpr int NT = K / 16;

    const int bm = blockIdx.y, bn = blockIdx.x, bz = blockIdx.z;

    const float* A;
    const float* Bp;
    if (MODE == 0)      { A = g_xn + (size_t)bm * 128 * K;                       Bp = g_wq; }
    else if (MODE == 1) { A = g_cn + ((size_t)bz * SEQ_K + (size_t)bm * 128) * K;
                          Bp = g_wkv + (size_t)(bz % ROUTES) * DHID * K; }
    else                { A = g_ao + (size_t)bm * 128 * K;                       Bp = g_wo; }
    Bp += (size_t)bn * 128 * K;

    __shared__ float As[3][2048];
    __shared__ float Bs[3][2048];

    const int tid  = threadIdx.x;
    const int lane = tid & 31, warp = tid >> 5;
    const int wm = warp >> 2, wn = warp & 3;     // 2 x 4 warp grid
    const int r  = lane >> 2, cq = lane & 3;

    // loader: 512 16B chunks per matrix, 2 per thread
    const int ch0 = tid, ch1 = tid + 256;
    const int lr0 = ch0 >> 2, lg0 = ch0 & 3;
    const int lr1 = ch1 >> 2, lg1 = ch1 & 3;
    const int ld0 = lr0 * 16 + ((lg0 ^ ((lr0 >> 1) & 3)) << 2);
    const int ld1 = lr1 * 16 + ((lg1 ^ ((lr1 >> 1) & 3)) << 2);
    const size_t ls0 = (size_t)lr0 * K + (lg0 << 2);
    const size_t ls1 = (size_t)lr1 * K + (lg1 << 2);

    // fragment base offsets + swizzle keys
    int offA[4], xA[4], offB[4], xB[4];
    #pragma unroll
    for (int mt = 0; mt < 4; mt++) {
        int m = wm * 64 + mt * 16 + r;
        offA[mt] = m * 16; xA[mt] = ((m >> 1) & 3) << 2;
    }
    #pragma unroll
    for (int nt = 0; nt < 4; nt++) {
        int n = wn * 32 + nt * 8 + r;
        offB[nt] = n * 16; xB[nt] = ((n >> 1) & 3) << 2;
    }

    float c[4][4][4];
    #pragma unroll
    for (int mt = 0; mt < 4; mt++)
        #pragma unroll
        for (int nt = 0; nt < 4; nt++)
            #pragma unroll
            for (int i = 0; i < 4; i++) c[mt][nt][i] = 0.f;

    // preload stages 0,1
    #pragma unroll
    for (int s = 0; s < 2; s++) {
        int k0 = s * 16;
        cp16(&As[s][ld0], A  + ls0 + k0);
        cp16(&As[s][ld1], A  + ls1 + k0);
        cp16(&Bs[s][ld0], Bp + ls0 + k0);
        cp16(&Bs[s][ld1], Bp + ls1 + k0);
        asm volatile("cp.async.commit_group;");
    }

    int scm = 0, sld = 2;
    #pragma unroll 1
    for (int t = 0; t < NT; t++) {
        asm volatile("cp.async.wait_group 1;");
        __syncthreads();

        if (t + 2 < NT) {
            int k0 = (t + 2) * 16;
            cp16(&As[sld][ld0], A  + ls0 + k0);
            cp16(&As[sld][ld1], A  + ls1 + k0);
            cp16(&Bs[sld][ld0], Bp + ls0 + k0);
            cp16(&Bs[sld][ld1], Bp + ls1 + k0);
        }
        asm volatile("cp.async.commit_group;");

        const float* as = As[scm];
        const float* bs = Bs[scm];
        #pragma unroll
        for (int ks = 0; ks < 16; ks += 8) {
            uint32_t af[4][4], bf[4][2];
            #pragma unroll
            for (int mt = 0; mt < 4; mt++) {
                int p = offA[mt] + ((ks + cq) ^ xA[mt]);
                af[mt][0] = __float_as_uint(as[p]);
                af[mt][1] = __float_as_uint(as[p + 128]);
                af[mt][2] = __float_as_uint(as[p ^ 4]);
                af[mt][3] = __float_as_uint(as[(p ^ 4) + 128]);
            }
            #pragma unroll
            for (int nt = 0; nt < 4; nt++) {
                int p = offB[nt] + ((ks + cq) ^ xB[nt]);
                bf[nt][0] = __float_as_uint(bs[p]);
                bf[nt][1] = __float_as_uint(bs[p ^ 4]);
            }
            #pragma unroll
            for (int mt = 0; mt < 4; mt++)
                #pragma unroll
                for (int nt = 0; nt < 4; nt++)
                    mma8(c[mt][nt], af[mt], bf[nt]);
        }
        scm = (scm == 2) ? 0 : scm + 1;
        sld = (sld == 2) ? 0 : sld + 1;
    }

    // epilogue
    #pragma unroll
    for (int mt = 0; mt < 4; mt++) {
        #pragma unroll
        for (int i = 0; i < 2; i++) {
            const int m = bm * 128 + wm * 64 + mt * 16 + r + i * 8;
            float srow = 0.f;
            if (MODE == 0) srow = sc[m] * 0.125f;
            if (MODE == 1) srow = sc[(size_t)bz * SEQ_K + m];
            #pragma unroll
            for (int nt = 0; nt < 4; nt++) {
                #pragma unroll
                for (int j = 0; j < 2; j++) {
                    const int o = bn * 128 + wn * 32 + nt * 8 + 2 * cq + j;
                    float v = c[mt][nt][i * 2 + j];
                    if (MODE == 0) {
                        int b = m >> 10, nn = m & 1023;
                        int h = o >> 6,  d  = o & 63;
                        g_q[(((size_t)(b * NHEAD + h)) * SEQ_N + nn) * DHEAD + d] = v * srow;
                    } else if (MODE == 1) {
                        int hp = o >> 7, dd = o & 127;
                        int b = bz / ROUTES, rt = bz % ROUTES;
                        size_t base = (((size_t)(b * NHEAD + rt * HPR + hp)) * SEQ_K + m) * DHEAD;
                        if (dd < DHEAD) g_k[base + dd]         = v * srow;
                        else            g_v[base + dd - DHEAD] = v * srow;
                    } else {
                        out[(size_t)m * DIMF + o] = v;
                    }
                }
            }
        }
    }
}

// ---------------- flash attention (fp32, single pass) ----------------
__global__ void __launch_bounds__(256) attn_kernel(const float* __restrict__ nullkv)
{
    const int bh    = blockIdx.y;
    const int h     = bh & (NHEAD - 1);
    const int qbase = blockIdx.x * 32;
    const int tid = threadIdx.x, lane = tid & 31, w = tid >> 5;

    __shared__ float KVs[64][65];
    __shared__ float qs[32][64];
    __shared__ float ps[32][64];
    __shared__ float nk_s[64], nv_s[64];

    const float* qg = g_q + ((size_t)bh * SEQ_N + qbase) * DHEAD;
    #pragma unroll
    for (int i = 0; i < 2; i++) {
        int idx = tid + i * 256;
        int rr = idx >> 4, c = (idx & 15) << 2;
        float4 v = *(const float4*)(qg + (size_t)rr * DHEAD + c);
        qs[rr][c] = v.x; qs[rr][c+1] = v.y; qs[rr][c+2] = v.z; qs[rr][c+3] = v.w;
    }
    if (tid < 64)       nk_s[tid]      = nullkv[h * DHEAD + tid];
    else if (tid < 128) nv_s[tid - 64] = nullkv[NHEAD * DHEAD + h * DHEAD + (tid - 64)];
    __syncthreads();

    float m[4], l[4], o0[4], o1[4];
    #pragma unroll
    for (int rr = 0; rr < 4; rr++) {
        int row = w * 4 + rr;
        float p = qs[row][lane] * nk_s[lane] + qs[row][lane + 32] * nk_s[lane + 32];
        #pragma unroll
        for (int off = 16; off; off >>= 1) p += __shfl_xor_sync(0xffffffffu, p, off);
        m[rr] = p; l[rr] = 1.f;
        o0[rr] = nv_s[lane]; o1[rr] = nv_s[lane + 32];
    }

    const float* kg = g_k + (size_t)bh * SEQ_K * DHEAD;
    const float* vg = g_v + (size_t)bh * SEQ_K * DHEAD;

    for (int t = 0; t < 16; t++) {
        __syncthreads();
        #pragma unroll
        for (int i = 0; i < 4; i++) {
            int idx = tid + i * 256;
            int rr = idx >> 4, c = (idx & 15) << 2;
            float4 kv4 = *(const float4*)(kg + (size_t)(t * 64 + rr) * DHEAD + c);
            KVs[rr][c] = kv4.x; KVs[rr][c+1] = kv4.y; KVs[rr][c+2] = kv4.z; KVs[rr][c+3] = kv4.w;
        }
        __syncthreads();

        float sa[4] = {0,0,0,0}, sb[4] = {0,0,0,0};
        #pragma unroll
        for (int d = 0; d < 64; d++) {
            float ka = KVs[lane][d], kb = KVs[lane + 32][d];
            #pragma unroll
            for (int rr = 0; rr < 4; rr++) {
                float qv = qs[w * 4 + rr][d];
                sa[rr] = fmaf(qv, ka, sa[rr]);
                sb[rr] = fmaf(qv, kb, sb[rr]);
            }
        }

        #pragma unroll
        for (int rr = 0; rr < 4; rr++) {
            float mt = fmaxf(sa[rr], sb[rr]);
            #pragma unroll
            for (int off = 16; off; off >>= 1)
                mt = fmaxf(mt, __shfl_xor_sync(0xffffffffu, mt, off));
            float mn   = fmaxf(m[rr], mt);
            float corr = __expf(m[rr] - mn);
            float pa   = __expf(sa[rr] - mn);
            float pb   = __expf(sb[rr] - mn);
            float psum = pa + pb;
            #pragma unroll
            for (int off = 16; off; off >>= 1)
                psum += __shfl_xor_sync(0xffffffffu, psum, off);
            l[rr] = l[rr] * corr + psum;
            o0[rr] *= corr; o1[rr] *= corr;
            m[rr] = mn;
            ps[w * 4 + rr][lane]      = pa;
            ps[w * 4 + rr][lane + 32] = pb;
        }
        __syncwarp();

        __syncthreads();
        #pragma unroll
        for (int i = 0; i < 4; i++) {
            int idx = tid + i * 256;
            int rr = idx >> 4, c = (idx & 15) << 2;
            float4 vv4 = *(const float4*)(vg + (size_t)(t * 64 + rr) * DHEAD + c);
            KVs[rr][c] = vv4.x; KVs[rr][c+1] = vv4.y; KVs[rr][c+2] = vv4.z; KVs[rr][c+3] = vv4.w;
        }
        __syncthreads();

        #pragma unroll 8
        for (int j = 0; j < 64; j++) {
            float v0 = KVs[j][lane], v1 = KVs[j][lane + 32];
            #pragma unroll
            for (int rr = 0; rr < 4; rr++) {
                float p = ps[w * 4 + rr][j];
                o0[rr] = fmaf(p, v0, o0[rr]);
                o1[rr] = fmaf(p, v1, o1[rr]);
            }
        }
    }

    const int b = bh >> 4;
    #pragma unroll
    for (int rr = 0; rr < 4; rr++) {
        int n = qbase + w * 4 + rr;
        float inv = 1.f / l[rr];
        size_t base = ((size_t)(b * SEQ_N + n)) * DHID + h * DHEAD;
        g_ao[base + lane]      = tf32r(o0[rr] * inv);
        g_ao[base + lane + 32] = tf32r(o1[rr] * inv);
    }
}

// ---------------- launch ----------------
extern "C" void kernel_launch(void* const* d_in, const int* in_sizes, int n_in,
                              void* d_out, int out_size)
{
    const float* x      = (const float*)d_in[0];
    const float* ctx    = (const float*)d_in[1];
    const float* skv    = (const float*)d_in[2];
    const float* sq     = (const float*)d_in[3];
    const float* gamma  = (const float*)d_in[4];
    const float* nullkv = (const float*)d_in[5];
    const float* Wq     = (const float*)d_in[6];
    const float* Wkv    = (const float*)d_in[7];
    const float* Wo     = (const float*)d_in[8];
    float* out = (float*)d_out;

    float* xn;  cudaGetSymbolAddress((void**)&xn,  g_xn);
    float* cn;  cudaGetSymbolAddress((void**)&cn,  g_cn);
    float* wq;  cudaGetSymbolAddress((void**)&wq,  g_wq);
    float* wkv; cudaGetSymbolAddress((void**)&wkv, g_wkv);
    float* wo;  cudaGetSymbolAddress((void**)&wo,  g_wo);

    // round weights to tf32 (rna)
    {
        int n4;
        n4 = (DHID * DIMF) / 4;
        round_tf32_kernel<<<(n4 + 255) / 256, 256>>>((const float4*)Wq,  (float4*)wq,  n4);
        n4 = (2 * DHID * DIMF) / 4;
        round_tf32_kernel<<<(n4 + 255) / 256, 256>>>((const float4*)Wkv, (float4*)wkv, n4);
        n4 = (DIMF * DHID) / 4;
        round_tf32_kernel<<<(n4 + 255) / 256, 256>>>((const float4*)Wo,  (float4*)wo,  n4);
    }

    rmsnorm_kernel<<<BATCH * SEQ_N, 256>>>(x, gamma, xn);
    rmsnorm_kernel<<<BATCH * ROUTES * SEQ_K, 256>>>(ctx, gamma, cn);

    // Q projection: (4096 x 1024 x 2048)
    gemm_tc<0><<<dim3(DHID / 128, (BATCH * SEQ_N) / 128, 1), 256>>>(sq, nullptr);
    // KV projection: 8 x (1024 x 1024 x 2048)
    gemm_tc<1><<<dim3(DHID / 128, SEQ_K / 128, BATCH * ROUTES), 256>>>(skv, nullptr);
    // attention
    attn_kernel<<<dim3(SEQ_N / 32, BATCH * NHEAD), 256>>>(nullkv);
    // output projection: (4096 x 2048 x 1024)
    gemm_tc<2><<<dim3(DIMF / 128, (BATCH * SEQ_N) / 128, 1), 256>>>(nullptr, out);
}

// round 3
// speedup vs baseline: 3.6788x; 1.6591x over previous
#include <cuda_runtime.h>
#include <math.h>
#include <stdint.h>

#define BATCH 4
#define SEQ_N 1024
#define SEQ_K 1024
#define DIMF  2048
#define NHEAD 16
#define DHEAD 64
#define ROUTES 2
#define HPR   (NHEAD/ROUTES)
#define DHID  (NHEAD*DHEAD)   // 1024

// ---------------- scratch (static device allocations) ----------------
__device__ float g_xn[(size_t)BATCH*SEQ_N*DIMF];           // normed x, tf32-rounded
__device__ float g_cn[(size_t)BATCH*ROUTES*SEQ_K*DIMF];    // normed context, tf32-rounded
__device__ float g_q [(size_t)BATCH*NHEAD*SEQ_N*DHEAD];    // (b,h,n,d)  tf32, scaled score_q/8
__device__ float g_k [(size_t)BATCH*NHEAD*SEQ_K*DHEAD];    // (b,h,nk,d) tf32, scaled score_kv
__device__ float g_v [(size_t)BATCH*NHEAD*SEQ_K*DHEAD];    // tf32, scaled score_kv
__device__ float g_ao[(size_t)BATCH*SEQ_N*DHID];           // attn out, tf32-rounded
__device__ float g_wq [(size_t)DHID*DIMF];                 // tf32-rounded weights
__device__ float g_wkv[(size_t)2*DHID*DIMF];
__device__ float g_wo [(size_t)DIMF*DHID];

// ---------------- helpers ----------------
__device__ __forceinline__ float tf32r(float x) {
    uint32_t u; asm("cvt.rna.tf32.f32 %0, %1;" : "=r"(u) : "f"(x));
    return __uint_as_float(u);
}
__device__ __forceinline__ void cp16(void* dst_smem, const void* src) {
    uint32_t d = (uint32_t)__cvta_generic_to_shared(dst_smem);
    asm volatile("cp.async.cg.shared.global [%0], [%1], 16;" :: "r"(d), "l"(src));
}
__device__ __forceinline__ void mma8(float* c, const uint32_t* a, const uint32_t* b) {
    asm volatile("mma.sync.aligned.m16n8k8.row.col.f32.tf32.tf32.f32 "
        "{%0,%1,%2,%3},{%4,%5,%6,%7},{%8,%9},{%0,%1,%2,%3};"
        : "+f"(c[0]), "+f"(c[1]), "+f"(c[2]), "+f"(c[3])
        : "r"(a[0]), "r"(a[1]), "r"(a[2]), "r"(a[3]), "r"(b[0]), "r"(b[1]));
}

// ---------------- tf32 rounding prep (weights) ----------------
__global__ void __launch_bounds__(256) round_tf32_kernel(
    const float4* __restrict__ in, float4* __restrict__ out, int n4)
{
    int i = blockIdx.x * 256 + threadIdx.x;
    if (i < n4) {
        float4 v = in[i];
        v.x = tf32r(v.x); v.y = tf32r(v.y); v.z = tf32r(v.z); v.w = tf32r(v.w);
        out[i] = v;
    }
}

// ---------------- RMS norm (tf32-rounded output) ----------------
__global__ void __launch_bounds__(256) rmsnorm_kernel(
    const float* __restrict__ in, const float* __restrict__ gamma,
    float* __restrict__ out)
{
    const long row = blockIdx.x;
    const float4* xr = (const float4*)(in + row * (long)DIMF);
    float4*       orow = (float4*)(out + row * (long)DIMF);
    const float4* g4 = (const float4*)gamma;
    const int t = threadIdx.x;

    float4 v0 = xr[t];
    float4 v1 = xr[t + 256];
    float ss = v0.x*v0.x + v0.y*v0.y + v0.z*v0.z + v0.w*v0.w
             + v1.x*v1.x + v1.y*v1.y + v1.z*v1.z + v1.w*v1.w;
    #pragma unroll
    for (int o = 16; o; o >>= 1) ss += __shfl_xor_sync(0xffffffffu, ss, o);
    __shared__ float red[8];
    if ((t & 31) == 0) red[t >> 5] = ss;
    __syncthreads();
    float tot = 0.f;
    #pragma unroll
    for (int i = 0; i < 8; i++) tot += red[i];
    const float s = sqrtf((float)DIMF) / fmaxf(sqrtf(tot), 1e-12f);

    float4 ga = g4[t], gb = g4[t + 256];
    orow[t]       = make_float4(tf32r(v0.x*s*ga.x), tf32r(v0.y*s*ga.y),
                                tf32r(v0.z*s*ga.z), tf32r(v0.w*s*ga.w));
    orow[t + 256] = make_float4(tf32r(v1.x*s*gb.x), tf32r(v1.y*s*gb.y),
                                tf32r(v1.z*s*gb.z), tf32r(v1.w*s*gb.w));
}

// ---------------- tf32 tensor-core GEMM, C(M,N) = A(M,K) * B(N,K)^T ----------------
template <int MODE>
__global__ void __launch_bounds__(256) gemm_tc(
    const float* __restrict__ sc, float* __restrict__ out)
{
    constexpr int K  = (MODE == 2) ? DHID : DIMF;
    constexpr int NT = K / 16;

    const int bm = blockIdx.y, bn = blockIdx.x, bz = blockIdx.z;

    const float* A;
    const float* Bp;
    if (MODE == 0)      { A = g_xn + (size_t)bm * 128 * K;                       Bp = g_wq; }
    else if (MODE == 1) { A = g_cn + ((size_t)bz * SEQ_K + (size_t)bm * 128) * K;
                          Bp = g_wkv + (size_t)(bz % ROUTES) * DHID * K; }
    else                { A = g_ao + (size_t)bm * 128 * K;                       Bp = g_wo; }
    Bp += (size_t)bn * 128 * K;

    __shared__ float As[3][2048];
    __shared__ float Bs[3][2048];

    const int tid  = threadIdx.x;
    const int lane = tid & 31, warp = tid >> 5;
    const int wm = warp >> 2, wn = warp & 3;
    const int r  = lane >> 2, cq = lane & 3;

    const int ch0 = tid, ch1 = tid + 256;
    const int lr0 = ch0 >> 2, lg0 = ch0 & 3;
    const int lr1 = ch1 >> 2, lg1 = ch1 & 3;
    const int ld0 = lr0 * 16 + ((lg0 ^ ((lr0 >> 1) & 3)) << 2);
    const int ld1 = lr1 * 16 + ((lg1 ^ ((lr1 >> 1) & 3)) << 2);
    const size_t ls0 = (size_t)lr0 * K + (lg0 << 2);
    const size_t ls1 = (size_t)lr1 * K + (lg1 << 2);

    int offA[4], xA[4], offB[4], xB[4];
    #pragma unroll
    for (int mt = 0; mt < 4; mt++) {
        int m = wm * 64 + mt * 16 + r;
        offA[mt] = m * 16; xA[mt] = ((m >> 1) & 3) << 2;
    }
    #pragma unroll
    for (int nt = 0; nt < 4; nt++) {
        int n = wn * 32 + nt * 8 + r;
        offB[nt] = n * 16; xB[nt] = ((n >> 1) & 3) << 2;
    }

    float c[4][4][4];
    #pragma unroll
    for (int mt = 0; mt < 4; mt++)
        #pragma unroll
        for (int nt = 0; nt < 4; nt++)
            #pragma unroll
            for (int i = 0; i < 4; i++) c[mt][nt][i] = 0.f;

    #pragma unroll
    for (int s = 0; s < 2; s++) {
        int k0 = s * 16;
        cp16(&As[s][ld0], A  + ls0 + k0);
        cp16(&As[s][ld1], A  + ls1 + k0);
        cp16(&Bs[s][ld0], Bp + ls0 + k0);
        cp16(&Bs[s][ld1], Bp + ls1 + k0);
        asm volatile("cp.async.commit_group;");
    }

    int scm = 0, sld = 2;
    #pragma unroll 1
    for (int t = 0; t < NT; t++) {
        asm volatile("cp.async.wait_group 1;");
        __syncthreads();

        if (t + 2 < NT) {
            int k0 = (t + 2) * 16;
            cp16(&As[sld][ld0], A  + ls0 + k0);
            cp16(&As[sld][ld1], A  + ls1 + k0);
            cp16(&Bs[sld][ld0], Bp + ls0 + k0);
            cp16(&Bs[sld][ld1], Bp + ls1 + k0);
        }
        asm volatile("cp.async.commit_group;");

        const float* as = As[scm];
        const float* bs = Bs[scm];
        #pragma unroll
        for (int ks = 0; ks < 16; ks += 8) {
            uint32_t af[4][4], bf[4][2];
            #pragma unroll
            for (int mt = 0; mt < 4; mt++) {
                int p = offA[mt] + ((ks + cq) ^ xA[mt]);
                af[mt][0] = __float_as_uint(as[p]);
                af[mt][1] = __float_as_uint(as[p + 128]);
                af[mt][2] = __float_as_uint(as[p ^ 4]);
                af[mt][3] = __float_as_uint(as[(p ^ 4) + 128]);
            }
            #pragma unroll
            for (int nt = 0; nt < 4; nt++) {
                int p = offB[nt] + ((ks + cq) ^ xB[nt]);
                bf[nt][0] = __float_as_uint(bs[p]);
                bf[nt][1] = __float_as_uint(bs[p ^ 4]);
            }
            #pragma unroll
            for (int mt = 0; mt < 4; mt++)
                #pragma unroll
                for (int nt = 0; nt < 4; nt++)
                    mma8(c[mt][nt], af[mt], bf[nt]);
        }
        scm = (scm == 2) ? 0 : scm + 1;
        sld = (sld == 2) ? 0 : sld + 1;
    }

    #pragma unroll
    for (int mt = 0; mt < 4; mt++) {
        #pragma unroll
        for (int i = 0; i < 2; i++) {
            const int m = bm * 128 + wm * 64 + mt * 16 + r + i * 8;
            float srow = 0.f;
            if (MODE == 0) srow = sc[m] * 0.125f;
            if (MODE == 1) srow = sc[(size_t)bz * SEQ_K + m];
            #pragma unroll
            for (int nt = 0; nt < 4; nt++) {
                #pragma unroll
                for (int j = 0; j < 2; j++) {
                    const int o = bn * 128 + wn * 32 + nt * 8 + 2 * cq + j;
                    float v = c[mt][nt][i * 2 + j];
                    if (MODE == 0) {
                        int b = m >> 10, nn = m & 1023;
                        int h = o >> 6,  d  = o & 63;
                        g_q[(((size_t)(b * NHEAD + h)) * SEQ_N + nn) * DHEAD + d] =
                            tf32r(v * srow);
                    } else if (MODE == 1) {
                        int hp = o >> 7, dd = o & 127;
                        int b = bz / ROUTES, rt = bz % ROUTES;
                        size_t base = (((size_t)(b * NHEAD + rt * HPR + hp)) * SEQ_K + m) * DHEAD;
                        if (dd < DHEAD) g_k[base + dd]         = tf32r(v * srow);
                        else            g_v[base + dd - DHEAD] = tf32r(v * srow);
                    } else {
                        out[(size_t)m * DIMF + o] = v;
                    }
                }
            }
        }
    }
}

// ---------------- tensor-core flash attention ----------------
// grid (SEQ_N/128, BATCH*NHEAD), 256 threads = 8 warps, 16 q-rows per warp.
// smem (floats):
//   qs [128][68]          0      .. 8704
//   ps [8][16][68]        8704   .. 17408   (per-warp private P strips)
//   ks [2][64][68]        17408  .. 26112
//   vs [2][64][72]        26112  .. 35328   ([key][dim], feeds B-frag directly)
//   nk/nv [64]+[64]       35328  .. 35456
#define ATTN_SMEM_FLOATS 35456
#define ATTN_SMEM_BYTES  (ATTN_SMEM_FLOATS * 4)

__global__ void __launch_bounds__(256, 1) attn_tc(const float* __restrict__ nullkv)
{
    extern __shared__ float smf[];
    float* qs = smf;
    float* ps = smf + 8704;
    float* ks = smf + 17408;
    float* vs = smf + 26112;
    float* nk = smf + 35328;
    float* nv = smf + 35392;

    const int bh = blockIdx.y, h = bh & (NHEAD - 1);
    const int qbase = blockIdx.x * 128;
    const int tid = threadIdx.x, lane = tid & 31, w = tid >> 5;
    const int g = lane >> 2, cq = lane & 3;

    const float* qg = g_q + ((size_t)bh * SEQ_N + qbase) * DHEAD;
    const float* kg = g_k + (size_t)bh * SEQ_K * DHEAD;
    const float* vg = g_v + (size_t)bh * SEQ_K * DHEAD;

    // load Q (already tf32-rounded in producer)
    #pragma unroll
    for (int i = 0; i < 8; i++) {
        int idx = tid + i * 256;                 // 2048 float4 chunks
        int r = idx >> 4, c = (idx & 15) << 2;
        float4 v = *(const float4*)(qg + (size_t)r * DHEAD + c);
        float* d = qs + r * 68 + c;
        d[0] = v.x; d[1] = v.y; d[2] = v.z; d[3] = v.w;
    }
    if (tid < 64)       nk[tid]      = nullkv[h * DHEAD + tid];
    else if (tid < 128) nv[tid - 64] = nullkv[NHEAD * DHEAD + h * DHEAD + (tid - 64)];

    // preload tile 0
    #pragma unroll
    for (int i = 0; i < 4; i++) {
        int idx = tid + i * 256;                 // 1024 chunks
        int r = idx >> 4, c = (idx & 15) << 2;
        cp16(ks + r * 68 + c, kg + (size_t)r * DHEAD + c);
        cp16(vs + r * 72 + c, vg + (size_t)r * DHEAD + c);
    }
    asm volatile("cp.async.commit_group;");
    __syncthreads();

    // null-key init: m = q.nullk, l = 1, O = nullv
    float m0, m1, l0 = 1.f, l1 = 1.f;
    {
        int row = w * 16 + (lane & 15);
        int half = (lane >> 4) * 32;
        float s = 0.f;
        #pragma unroll
        for (int d = 0; d < 32; d++)
            s = fmaf(qs[row * 68 + half + d], nk[half + d], s);
        s += __shfl_xor_sync(0xffffffffu, s, 16);
        m0 = __shfl_sync(0xffffffffu, s, g);
        m1 = __shfl_sync(0xffffffffu, s, g + 8);
    }
    float o[8][4];
    #pragma unroll
    for (int nt = 0; nt < 8; nt++) {
        float va = nv[nt * 8 + 2 * cq], vb = nv[nt * 8 + 2 * cq + 1];
        o[nt][0] = va; o[nt][1] = vb; o[nt][2] = va; o[nt][3] = vb;
    }

    const float* qw = qs + (w * 16) * 68;
    float* psw = ps + (w * 16) * 68;

    #pragma unroll 1
    for (int t = 0; t < 16; t++) {
        asm volatile("cp.async.wait_group 0;");
        __syncthreads();

        if (t + 1 < 16) {
            float* kd = ks + ((t + 1) & 1) * 4352;
            float* vd = vs + ((t + 1) & 1) * 4608;
            const float* kgt = kg + (size_t)(t + 1) * 64 * DHEAD;
            const float* vgt = vg + (size_t)(t + 1) * 64 * DHEAD;
            #pragma unroll
            for (int i = 0; i < 4; i++) {
                int idx = tid + i * 256;
                int r = idx >> 4, c = (idx & 15) << 2;
                cp16(kd + r * 68 + c, kgt + (size_t)r * DHEAD + c);
                cp16(vd + r * 72 + c, vgt + (size_t)r * DHEAD + c);
            }
            asm volatile("cp.async.commit_group;");
        }

        const float* ksb = ks + (t & 1) * 4352;
        const float* vsb = vs + (t & 1) * 4608;

        // S = Q K^T   (warp: 16 rows x 64 keys)
        float s[8][4];
        #pragma unroll
        for (int nt = 0; nt < 8; nt++)
            s[nt][0] = s[nt][1] = s[nt][2] = s[nt][3] = 0.f;

        #pragma unroll
        for (int k8 = 0; k8 < 8; k8++) {
            int k0 = k8 * 8;
            uint32_t a[4];
            a[0] = __float_as_uint(qw[g * 68 + k0 + cq]);
            a[1] = __float_as_uint(qw[(g + 8) * 68 + k0 + cq]);
            a[2] = __float_as_uint(qw[g * 68 + k0 + cq + 4]);
            a[3] = __float_as_uint(qw[(g + 8) * 68 + k0 + cq + 4]);
            #pragma unroll
            for (int nt = 0; nt < 8; nt++) {
                uint32_t b[2];
                b[0] = __float_as_uint(ksb[(nt * 8 + g) * 68 + k0 + cq]);
                b[1] = __float_as_uint(ksb[(nt * 8 + g) * 68 + k0 + cq + 4]);
                mma8(s[nt], a, b);
            }
        }

        // online softmax (rows g and g+8, quad-reduced)
        float mx0 = -1e30f, mx1 = -1e30f;
        #pragma unroll
        for (int nt = 0; nt < 8; nt++) {
            mx0 = fmaxf(mx0, fmaxf(s[nt][0], s[nt][1]));
            mx1 = fmaxf(mx1, fmaxf(s[nt][2], s[nt][3]));
        }
        mx0 = fmaxf(mx0, __shfl_xor_sync(0xffffffffu, mx0, 1));
        mx0 = fmaxf(mx0, __shfl_xor_sync(0xffffffffu, mx0, 2));
        mx1 = fmaxf(mx1, __shfl_xor_sync(0xffffffffu, mx1, 1));
        mx1 = fmaxf(mx1, __shfl_xor_sync(0xffffffffu, mx1, 2));
        float mn0 = fmaxf(m0, mx0), mn1 = fmaxf(m1, mx1);
        float c0 = __expf(m0 - mn0), c1 = __expf(m1 - mn1);
        float p0 = 0.f, p1 = 0.f;
        #pragma unroll
        for (int nt = 0; nt < 8; nt++) {
            s[nt][0] = __expf(s[nt][0] - mn0);
            s[nt][1] = __expf(s[nt][1] - mn0);
            s[nt][2] = __expf(s[nt][2] - mn1);
            s[nt][3] = __expf(s[nt][3] - mn1);
            p0 += s[nt][0] + s[nt][1];
            p1 += s[nt][2] + s[nt][3];
        }
        p0 += __shfl_xor_sync(0xffffffffu, p0, 1);
        p0 += __shfl_xor_sync(0xffffffffu, p0, 2);
        p1 += __shfl_xor_sync(0xffffffffu, p1, 1);
        p1 += __shfl_xor_sync(0xffffffffu, p1, 2);
        l0 = l0 * c0 + p0; l1 = l1 * c1 + p1;
        m0 = mn0; m1 = mn1;
        #pragma unroll
        for (int nt = 0; nt < 8; nt++) {
            o[nt][0] *= c0; o[nt][1] *= c0;
            o[nt][2] *= c1; o[nt][3] *= c1;
        }

        // write P (tf32-rounded) to warp-private strip
        #pragma unroll
        for (int nt = 0; nt < 8; nt++) {
            *(float2*)(psw + g * 68 + nt * 8 + 2 * cq) =
                make_float2(tf32r(s[nt][0]), tf32r(s[nt][1]));
            *(float2*)(psw + (g + 8) * 68 + nt * 8 + 2 * cq) =
                make_float2(tf32r(s[nt][2]), tf32r(s[nt][3]));
        }
        __syncwarp();

        // O += P V
        #pragma unroll
        for (int k8 = 0; k8 < 8; k8++) {
            int k0 = k8 * 8;
            uint32_t a[4];
            a[0] = __float_as_uint(psw[g * 68 + k0 + cq]);
            a[1] = __float_as_uint(psw[(g + 8) * 68 + k0 + cq]);
            a[2] = __float_as_uint(psw[g * 68 + k0 + cq + 4]);
            a[3] = __float_as_uint(psw[(g + 8) * 68 + k0 + cq + 4]);
            #pragma unroll
            for (int nt = 0; nt < 8; nt++) {
                uint32_t b[2];
                b[0] = __float_as_uint(vsb[(k0 + cq) * 72 + nt * 8 + g]);
                b[1] = __float_as_uint(vsb[(k0 + cq + 4) * 72 + nt * 8 + g]);
                mma8(o[nt], a, b);
            }
        }
    }

    // write out (tf32-rounded for the O projection)
    const int b = bh >> 4;
    const float i0 = 1.f / l0, i1 = 1.f / l1;
    const int n0 = qbase + w * 16 + g;
    const size_t base0 = ((size_t)(b * SEQ_N + n0)) * DHID + h * DHEAD;
    const size_t base1 = ((size_t)(b * SEQ_N + n0 + 8)) * DHID + h * DHEAD;
    #pragma unroll
    for (int nt = 0; nt < 8; nt++) {
        int col = nt * 8 + 2 * cq;
        g_ao[base0 + col]     = tf32r(o[nt][0] * i0);
        g_ao[base0 + col + 1] = tf32r(o[nt][1] * i0);
        g_ao[base1 + col]     = tf32r(o[nt][2] * i1);
        g_ao[base1 + col + 1] = tf32r(o[nt][3] * i1);
    }
}

// ---------------- launch ----------------
extern "C" void kernel_launch(void* const* d_in, const int* in_sizes, int n_in,
                              void* d_out, int out_size)
{
    const float* x      = (const float*)d_in[0];
    const float* ctx    = (const float*)d_in[1];
    const float* skv    = (const float*)d_in[2];
    const float* sq     = (const float*)d_in[3];
    const float* gamma  = (const float*)d_in[4];
    const float* nullkv = (const float*)d_in[5];
    const float* Wq     = (const float*)d_in[6];
    const float* Wkv    = (const float*)d_in[7];
    const float* Wo     = (const float*)d_in[8];
    float* out = (float*)d_out;

    float* xn;  cudaGetSymbolAddress((void**)&xn,  g_xn);
    float* cn;  cudaGetSymbolAddress((void**)&cn,  g_cn);
    float* wq;  cudaGetSymbolAddress((void**)&wq,  g_wq);
    float* wkv; cudaGetSymbolAddress((void**)&wkv, g_wkv);
    float* wo;  cudaGetSymbolAddress((void**)&wo,  g_wo);

    static int smem_set = 0;
    if (!smem_set) {
        cudaFuncSetAttribute(attn_tc, cudaFuncAttributeMaxDynamicSharedMemorySize,
                             ATTN_SMEM_BYTES);
        smem_set = 1;
    }

    {
        int n4;
        n4 = (DHID * DIMF) / 4;
        round_tf32_kernel<<<(n4 + 255) / 256, 256>>>((const float4*)Wq,  (float4*)wq,  n4);
        n4 = (2 * DHID * DIMF) / 4;
        round_tf32_kernel<<<(n4 + 255) / 256, 256>>>((const float4*)Wkv, (float4*)wkv, n4);
        n4 = (DIMF * DHID) / 4;
        round_tf32_kernel<<<(n4 + 255) / 256, 256>>>((const float4*)Wo,  (float4*)wo,  n4);
    }

    rmsnorm_kernel<<<BATCH * SEQ_N, 256>>>(x, gamma, xn);
    rmsnorm_kernel<<<BATCH * ROUTES * SEQ_K, 256>>>(ctx, gamma, cn);

    gemm_tc<0><<<dim3(DHID / 128, (BATCH * SEQ_N) / 128, 1), 256>>>(sq, nullptr);
    gemm_tc<1><<<dim3(DHID / 128, SEQ_K / 128, BATCH * ROUTES), 256>>>(skv, nullptr);

    attn_tc<<<dim3(SEQ_N / 128, BATCH * NHEAD), 256, ATTN_SMEM_BYTES>>>(nullkv);

    gemm_tc<2><<<dim3(DIMF / 128, (BATCH * SEQ_N) / 128, 1), 256>>>(nullptr, out);
}

// round 5
// speedup vs baseline: 5.6036x; 1.5232x over previous
#include <cuda_runtime.h>
#include <cuda_fp16.h>
#include <math.h>
#include <stdint.h>

#define BATCH 4
#define SEQ_N 1024
#define SEQ_K 1024
#define DIMF  2048
#define NHEAD 16
#define DHEAD 64
#define ROUTES 2
#define HPR   (NHEAD/ROUTES)
#define DHID  (NHEAD*DHEAD)   // 1024

// ---------------- scratch (static device allocations) ----------------
__device__ __half h_xn[(size_t)BATCH*SEQ_N*DIMF];          // normed x (fp16)
__device__ __half h_cn[(size_t)BATCH*ROUTES*SEQ_K*DIMF];   // normed context (fp16)
__device__ float  g_q [(size_t)BATCH*NHEAD*SEQ_N*DHEAD];   // tf32-rounded, scaled score_q/8
__device__ float  g_k [(size_t)BATCH*NHEAD*SEQ_K*DHEAD];   // tf32-rounded, scaled score_kv
__device__ float  g_v [(size_t)BATCH*NHEAD*SEQ_K*DHEAD];
__device__ __half h_ao[(size_t)BATCH*SEQ_N*DHID];          // attn out (fp16)
__device__ __half h_wq [(size_t)DHID*DIMF];                // fp16 weights
__device__ __half h_wkv[(size_t)2*DHID*DIMF];
__device__ __half h_wo [(size_t)DIMF*DHID];

// ---------------- helpers ----------------
__device__ __forceinline__ float tf32r(float x) {
    uint32_t u; asm("cvt.rna.tf32.f32 %0, %1;" : "=r"(u) : "f"(x));
    return __uint_as_float(u);
}
__device__ __forceinline__ void cp16(void* dst_smem, const void* src) {
    uint32_t d = (uint32_t)__cvta_generic_to_shared(dst_smem);
    asm volatile("cp.async.cg.shared.global [%0], [%1], 16;" :: "r"(d), "l"(src));
}
__device__ __forceinline__ void mma8(float* c, const uint32_t* a, const uint32_t* b) {
    asm volatile("mma.sync.aligned.m16n8k8.row.col.f32.tf32.tf32.f32 "
        "{%0,%1,%2,%3},{%4,%5,%6,%7},{%8,%9},{%0,%1,%2,%3};"
        : "+f"(c[0]), "+f"(c[1]), "+f"(c[2]), "+f"(c[3])
        : "r"(a[0]), "r"(a[1]), "r"(a[2]), "r"(a[3]), "r"(b[0]), "r"(b[1]));
}
__device__ __forceinline__ void mma16h(float* c, const uint32_t* a, uint32_t b0, uint32_t b1) {
    asm volatile("mma.sync.aligned.m16n8k16.row.col.f32.f16.f16.f32 "
        "{%0,%1,%2,%3},{%4,%5,%6,%7},{%8,%9},{%0,%1,%2,%3};"
        : "+f"(c[0]), "+f"(c[1]), "+f"(c[2]), "+f"(c[3])
        : "r"(a[0]), "r"(a[1]), "r"(a[2]), "r"(a[3]), "r"(b0), "r"(b1));
}
__device__ __forceinline__ void ldsm4(uint32_t* r, uint32_t addr) {
    asm volatile("ldmatrix.sync.aligned.m8n8.x4.shared.b16 {%0,%1,%2,%3}, [%4];"
        : "=r"(r[0]), "=r"(r[1]), "=r"(r[2]), "=r"(r[3]) : "r"(addr));
}
__device__ __forceinline__ uint32_t s2u(const void* p) {
    uint32_t a;
    asm("{ .reg .u64 t; cvta.to.shared.u64 t, %1; cvt.u32.u64 %0, t; }"
        : "=r"(a) : "l"(p));
    return a;
}

// ---------------- weight fp32 -> fp16 prep ----------------
__global__ void __launch_bounds__(256) round_half_kernel(
    const float4* __restrict__ in, __half2* __restrict__ out, int n4)
{
    int i = blockIdx.x * 256 + threadIdx.x;
    if (i < n4) {
        float4 v = in[i];
        out[2 * i]     = __floats2half2_rn(v.x, v.y);
        out[2 * i + 1] = __floats2half2_rn(v.z, v.w);
    }
}

// ---------------- RMS norm (fp16 output) ----------------
__global__ void __launch_bounds__(256) rmsnorm_kernel(
    const float* __restrict__ in, const float* __restrict__ gamma,
    __half* __restrict__ out)
{
    const long row = blockIdx.x;
    const float4* xr = (const float4*)(in + row * (long)DIMF);
    const float4* g4 = (const float4*)gamma;
    const int t = threadIdx.x;

    float4 v0 = xr[2 * t];
    float4 v1 = xr[2 * t + 1];
    float ss = v0.x*v0.x + v0.y*v0.y + v0.z*v0.z + v0.w*v0.w
             + v1.x*v1.x + v1.y*v1.y + v1.z*v1.z + v1.w*v1.w;
    #pragma unroll
    for (int o = 16; o; o >>= 1) ss += __shfl_xor_sync(0xffffffffu, ss, o);
    __shared__ float red[8];
    if ((t & 31) == 0) red[t >> 5] = ss;
    __syncthreads();
    float tot = 0.f;
    #pragma unroll
    for (int i = 0; i < 8; i++) tot += red[i];
    const float s = sqrtf((float)DIMF) / fmaxf(sqrtf(tot), 1e-12f);

    float4 ga = g4[2 * t], gb = g4[2 * t + 1];
    __half2 o0 = __floats2half2_rn(v0.x*s*ga.x, v0.y*s*ga.y);
    __half2 o1 = __floats2half2_rn(v0.z*s*ga.z, v0.w*s*ga.w);
    __half2 o2 = __floats2half2_rn(v1.x*s*gb.x, v1.y*s*gb.y);
    __half2 o3 = __floats2half2_rn(v1.z*s*gb.z, v1.w*s*gb.w);
    uint4 pk;
    pk.x = *(uint32_t*)&o0; pk.y = *(uint32_t*)&o1;
    pk.z = *(uint32_t*)&o2; pk.w = *(uint32_t*)&o3;
    ((uint4*)(out + row * (long)DIMF))[t] = pk;
}

// ---------------- fp16 tensor-core GEMM, C(M,N) = A(M,K) * B(N,K)^T ----------------
// 128x128 tile, BK=64 halves (128B rows), 3-stage cp.async pipeline (96KB smem),
// 256 threads (8 warps 2x4), warp tile 64x32, ldmatrix fragment loads.
// swizzle: 16B group g of row r stored at group (g ^ (r&7)).
// MODE 0: Q proj  (A=h_xn, B=h_wq,  K=2048) -> g_q  fp32 tf32r, scaled score_q/8
// MODE 1: KV proj (A=h_cn, B=h_wkv, K=2048) -> g_k/g_v fp32 tf32r, scaled score_kv
// MODE 2: O proj  (A=h_ao, B=h_wo,  K=1024) -> d_out fp32
#define GH_STAGE 32768
#define GH_SMEM  (3 * GH_STAGE)

template <int MODE>
__global__ void __launch_bounds__(256, 1) gemm_fp16(
    const float* __restrict__ sc, float* __restrict__ out)
{
    constexpr int K  = (MODE == 2) ? DHID : DIMF;
    constexpr int NC = K / 64;

    extern __shared__ char smem[];
    const uint32_t smu = s2u(smem);

    const int bm = blockIdx.y, bn = blockIdx.x, bz = blockIdx.z;
    const int tid = threadIdx.x;
    const int lane = tid & 31, warp = tid >> 5;
    const int wm = warp >> 2, wn = warp & 3;
    const int g = lane >> 2, cq = lane & 3;

    const __half *A, *Bp;
    if (MODE == 0)      { A = h_xn + (size_t)bm * 128 * K;                        Bp = h_wq; }
    else if (MODE == 1) { A = h_cn + ((size_t)bz * SEQ_K + (size_t)bm * 128) * K;
                          Bp = h_wkv + (size_t)(bz & 1) * DHID * K; }
    else                { A = h_ao + (size_t)bm * 128 * K;                        Bp = h_wo; }
    Bp += (size_t)bn * 128 * K;

    // loader: per chunk, A 128 rows x 128B + B 128 rows x 128B
    const int lr = tid >> 3, lg = tid & 7;
    const int ldst = lr * 128 + ((lg ^ (lr & 7)) << 4);
    auto load_chunk = [&](int c, int st) {
        char* aB = smem + st * GH_STAGE;
        char* bB = aB + 16384;
        const size_t ko = (size_t)c * 64 + lg * 8;
        #pragma unroll
        for (int t4 = 0; t4 < 4; t4++)
            cp16(aB + ldst + t4 * 4096, A + (size_t)(lr + t4 * 32) * K + ko);
        #pragma unroll
        for (int t4 = 0; t4 < 4; t4++)
            cp16(bB + ldst + t4 * 4096, Bp + (size_t)(lr + t4 * 32) * K + ko);
    };

    // per-lane fragment addressing
    const int lrow = lane & 15, hi = lane >> 4;        // hi: +8 halves in k
    int moff[4], msw[4];
    #pragma unroll
    for (int mt = 0; mt < 4; mt++) {
        int r = wm * 64 + mt * 16 + lrow;
        moff[mt] = r * 128; msw[mt] = r & 7;
    }
    int noff2[2], nsw[2];
    #pragma unroll
    for (int p = 0; p < 2; p++) {
        int r = wn * 32 + p * 16 + lrow;
        noff2[p] = r * 128; nsw[p] = r & 7;
    }

    float c[4][4][4];
    #pragma unroll
    for (int mt = 0; mt < 4; mt++)
        #pragma unroll
        for (int nt = 0; nt < 4; nt++)
            #pragma unroll
            for (int i = 0; i < 4; i++) c[mt][nt][i] = 0.f;

    load_chunk(0, 0);
    asm volatile("cp.async.commit_group;");
    load_chunk(1, 1);
    asm volatile("cp.async.commit_group;");

    #pragma unroll 1
    for (int t = 0; t < NC; t++) {
        asm volatile("cp.async.wait_group 1;");
        __syncthreads();

        if (t + 2 < NC) load_chunk(t + 2, (t + 2) % 3);
        asm volatile("cp.async.commit_group;");

        const uint32_t ab = smu + (t % 3) * GH_STAGE;
        const uint32_t bb = ab + 16384;

        #pragma unroll
        for (int ks = 0; ks < 4; ks++) {
            const int kg = 2 * ks + hi;
            uint32_t af[4][4], bf[2][4];
            #pragma unroll
            for (int mt = 0; mt < 4; mt++)
                ldsm4(af[mt], ab + moff[mt] + ((kg ^ msw[mt]) << 4));
            #pragma unroll
            for (int p = 0; p < 2; p++)
                ldsm4(bf[p], bb + noff2[p] + ((kg ^ nsw[p]) << 4));
            #pragma unroll
            for (int mt = 0; mt < 4; mt++) {
                #pragma unroll
                for (int nt = 0; nt < 4; nt++)
                    mma16h(c[mt][nt], af[mt], bf[nt >> 1][nt & 1], bf[nt >> 1][(nt & 1) + 2]);
            }
        }
        __syncthreads();
    }

    // ---- epilogue ----
    #pragma unroll
    for (int mt = 0; mt < 4; mt++) {
        #pragma unroll
        for (int i = 0; i < 2; i++) {
            const int m = bm * 128 + wm * 64 + mt * 16 + g + i * 8;
            float srow = 0.f;
            if (MODE == 0) srow = sc[m] * 0.125f;
            if (MODE == 1) srow = sc[(size_t)bz * SEQ_K + m];
            #pragma unroll
            for (int nt = 0; nt < 4; nt++) {
                const int noff = (nt >> 1) * 16 + (nt & 1) * 8;
                #pragma unroll
                for (int j = 0; j < 2; j++) {
                    const int o = bn * 128 + wn * 32 + noff + 2 * cq + j;
                    float v = c[mt][nt][i * 2 + j];
                    if (MODE == 0) {
                        int b = m >> 10, nn = m & 1023;
                        int h = o >> 6,  d  = o & 63;
                        g_q[(((size_t)(b * NHEAD + h)) * SEQ_N + nn) * DHEAD + d] =
                            tf32r(v * srow);
                    } else if (MODE == 1) {
                        int hp = o >> 7, dd = o & 127;
                        int b = bz >> 1, rt = bz & 1;
                        size_t base = (((size_t)(b * NHEAD + rt * HPR + hp)) * SEQ_K + m) * DHEAD;
                        if (dd < DHEAD) g_k[base + dd]         = tf32r(v * srow);
                        else            g_v[base + dd - DHEAD] = tf32r(v * srow);
                    } else {
                        out[(size_t)m * DIMF + o] = v;
                    }
                }
            }
        }
    }
}

// ---------------- tensor-core flash attention (tf32, unchanged core) ----------------
#define ATTN_SMEM_FLOATS 35456
#define ATTN_SMEM_BYTES  (ATTN_SMEM_FLOATS * 4)

__global__ void __launch_bounds__(256, 1) attn_tc(const float* __restrict__ nullkv)
{
    extern __shared__ float smf[];
    float* qs = smf;
    float* ps = smf + 8704;
    float* ks = smf + 17408;
    float* vs = smf + 26112;
    float* nk = smf + 35328;
    float* nv = smf + 35392;

    const int bh = blockIdx.y, h = bh & (NHEAD - 1);
    const int qbase = blockIdx.x * 128;
    const int tid = threadIdx.x, lane = tid & 31, w = tid >> 5;
    const int g = lane >> 2, cq = lane & 3;

    const float* qg = g_q + ((size_t)bh * SEQ_N + qbase) * DHEAD;
    const float* kg = g_k + (size_t)bh * SEQ_K * DHEAD;
    const float* vg = g_v + (size_t)bh * SEQ_K * DHEAD;

    #pragma unroll
    for (int i = 0; i < 8; i++) {
        int idx = tid + i * 256;
        int r = idx >> 4, c = (idx & 15) << 2;
        float4 v = *(const float4*)(qg + (size_t)r * DHEAD + c);
        float* d = qs + r * 68 + c;
        d[0] = v.x; d[1] = v.y; d[2] = v.z; d[3] = v.w;
    }
    if (tid < 64)       nk[tid]      = nullkv[h * DHEAD + tid];
    else if (tid < 128) nv[tid - 64] = nullkv[NHEAD * DHEAD + h * DHEAD + (tid - 64)];

    #pragma unroll
    for (int i = 0; i < 4; i++) {
        int idx = tid + i * 256;
        int r = idx >> 4, c = (idx & 15) << 2;
        cp16(ks + r * 68 + c, kg + (size_t)r * DHEAD + c);
        cp16(vs + r * 72 + c, vg + (size_t)r * DHEAD + c);
    }
    asm volatile("cp.async.commit_group;");
    __syncthreads();

    float m0, m1, l0 = 1.f, l1 = 1.f;
    {
        int row = w * 16 + (lane & 15);
        int half = (lane >> 4) * 32;
        float s = 0.f;
        #pragma unroll
        for (int d = 0; d < 32; d++)
            s = fmaf(qs[row * 68 + half + d], nk[half + d], s);
        s += __shfl_xor_sync(0xffffffffu, s, 16);
        m0 = __shfl_sync(0xffffffffu, s, g);
        m1 = __shfl_sync(0xffffffffu, s, g + 8);
    }
    float o[8][4];
    #pragma unroll
    for (int nt = 0; nt < 8; nt++) {
        float va = nv[nt * 8 + 2 * cq], vb = nv[nt * 8 + 2 * cq + 1];
        o[nt][0] = va; o[nt][1] = vb; o[nt][2] = va; o[nt][3] = vb;
    }

    const float* qw = qs + (w * 16) * 68;
    float* psw = ps + (w * 16) * 68;

    #pragma unroll 1
    for (int t = 0; t < 16; t++) {
        asm volatile("cp.async.wait_group 0;");
        __syncthreads();

        if (t + 1 < 16) {
            float* kd = ks + ((t + 1) & 1) * 4352;
            float* vd = vs + ((t + 1) & 1) * 4608;
            const float* kgt = kg + (size_t)(t + 1) * 64 * DHEAD;
            const float* vgt = vg + (size_t)(t + 1) * 64 * DHEAD;
            #pragma unroll
            for (int i = 0; i < 4; i++) {
                int idx = tid + i * 256;
                int r = idx >> 4, c = (idx & 15) << 2;
                cp16(kd + r * 68 + c, kgt + (size_t)r * DHEAD + c);
                cp16(vd + r * 72 + c, vgt + (size_t)r * DHEAD + c);
            }
            asm volatile("cp.async.commit_group;");
        }

        const float* ksb = ks + (t & 1) * 4352;
        const float* vsb = vs + (t & 1) * 4608;

        float s[8][4];
        #pragma unroll
        for (int nt = 0; nt < 8; nt++)
            s[nt][0] = s[nt][1] = s[nt][2] = s[nt][3] = 0.f;

        #pragma unroll
        for (int k8 = 0; k8 < 8; k8++) {
            int k0 = k8 * 8;
            uint32_t a[4];
            a[0] = __float_as_uint(qw[g * 68 + k0 + cq]);
            a[1] = __float_as_uint(qw[(g + 8) * 68 + k0 + cq]);
            a[2] = __float_as_uint(qw[g * 68 + k0 + cq + 4]);
            a[3] = __float_as_uint(qw[(g + 8) * 68 + k0 + cq + 4]);
            #pragma unroll
            for (int nt = 0; nt < 8; nt++) {
                uint32_t b[2];
                b[0] = __float_as_uint(ksb[(nt * 8 + g) * 68 + k0 + cq]);
                b[1] = __float_as_uint(ksb[(nt * 8 + g) * 68 + k0 + cq + 4]);
                mma8(s[nt], a, b);
            }
        }

        float mx0 = -1e30f, mx1 = -1e30f;
        #pragma unroll
        for (int nt = 0; nt < 8; nt++) {
            mx0 = fmaxf(mx0, fmaxf(s[nt][0], s[nt][1]));
            mx1 = fmaxf(mx1, fmaxf(s[nt][2], s[nt][3]));
        }
        mx0 = fmaxf(mx0, __shfl_xor_sync(0xffffffffu, mx0, 1));
        mx0 = fmaxf(mx0, __shfl_xor_sync(0xffffffffu, mx0, 2));
        mx1 = fmaxf(mx1, __shfl_xor_sync(0xffffffffu, mx1, 1));
        mx1 = fmaxf(mx1, __shfl_xor_sync(0xffffffffu, mx1, 2));
        float mn0 = fmaxf(m0, mx0), mn1 = fmaxf(m1, mx1);
        float c0 = __expf(m0 - mn0), c1 = __expf(m1 - mn1);
        float p0 = 0.f, p1 = 0.f;
        #pragma unroll
        for (int nt = 0; nt < 8; nt++) {
            s[nt][0] = __expf(s[nt][0] - mn0);
            s[nt][1] = __expf(s[nt][1] - mn0);
            s[nt][2] = __expf(s[nt][2] - mn1);
            s[nt][3] = __expf(s[nt][3] - mn1);
            p0 += s[nt][0] + s[nt][1];
            p1 += s[nt][2] + s[nt][3];
        }
        p0 += __shfl_xor_sync(0xffffffffu, p0, 1);
        p0 += __shfl_xor_sync(0xffffffffu, p0, 2);
        p1 += __shfl_xor_sync(0xffffffffu, p1, 1);
        p1 += __shfl_xor_sync(0xffffffffu, p1, 2);
        l0 = l0 * c0 + p0; l1 = l1 * c1 + p1;
        m0 = mn0; m1 = mn1;
        #pragma unroll
        for (int nt = 0; nt < 8; nt++) {
            o[nt][0] *= c0; o[nt][1] *= c0;
            o[nt][2] *= c1; o[nt][3] *= c1;
        }

        #pragma unroll
        for (int nt = 0; nt < 8; nt++) {
            *(float2*)(psw + g * 68 + nt * 8 + 2 * cq) =
                make_float2(tf32r(s[nt][0]), tf32r(s[nt][1]));
            *(float2*)(psw + (g + 8) * 68 + nt * 8 + 2 * cq) =
                make_float2(tf32r(s[nt][2]), tf32r(s[nt][3]));
        }
        __syncwarp();

        #pragma unroll
        for (int k8 = 0; k8 < 8; k8++) {
            int k0 = k8 * 8;
            uint32_t a[4];
            a[0] = __float_as_uint(psw[g * 68 + k0 + cq]);
            a[1] = __float_as_uint(psw[(g + 8) * 68 + k0 + cq]);
            a[2] = __float_as_uint(psw[g * 68 + k0 + cq + 4]);
            a[3] = __float_as_uint(psw[(g + 8) * 68 + k0 + cq + 4]);
            #pragma unroll
            for (int nt = 0; nt < 8; nt++) {
                uint32_t b[2];
                b[0] = __float_as_uint(vsb[(k0 + cq) * 72 + nt * 8 + g]);
                b[1] = __float_as_uint(vsb[(k0 + cq + 4) * 72 + nt * 8 + g]);
                mma8(o[nt], a, b);
            }
        }
    }

    const int b = bh >> 4;
    const float i0 = 1.f / l0, i1 = 1.f / l1;
    const int n0 = qbase + w * 16 + g;
    const size_t base0 = ((size_t)(b * SEQ_N + n0)) * DHID + h * DHEAD;
    const size_t base1 = ((size_t)(b * SEQ_N + n0 + 8)) * DHID + h * DHEAD;
    #pragma unroll
    for (int nt = 0; nt < 8; nt++) {
        int col = nt * 8 + 2 * cq;
        *(__half2*)&h_ao[base0 + col] = __floats2half2_rn(o[nt][0] * i0, o[nt][1] * i0);
        *(__half2*)&h_ao[base1 + col] = __floats2half2_rn(o[nt][2] * i1, o[nt][3] * i1);
    }
}

// ---------------- launch ----------------
extern "C" void kernel_launch(void* const* d_in, const int* in_sizes, int n_in,
                              void* d_out, int out_size)
{
    const float* x      = (const float*)d_in[0];
    const float* ctx    = (const float*)d_in[1];
    const float* skv    = (const float*)d_in[2];
    const float* sq     = (const float*)d_in[3];
    const float* gamma  = (const float*)d_in[4];
    const float* nullkv = (const float*)d_in[5];
    const float* Wq     = (const float*)d_in[6];
    const float* Wkv    = (const float*)d_in[7];
    const float* Wo     = (const float*)d_in[8];
    float* out = (float*)d_out;

    __half* xn;  cudaGetSymbolAddress((void**)&xn,  h_xn);
    __half* cn;  cudaGetSymbolAddress((void**)&cn,  h_cn);
    __half* wq;  cudaGetSymbolAddress((void**)&wq,  h_wq);
    __half* wkv; cudaGetSymbolAddress((void**)&wkv, h_wkv);
    __half* wo;  cudaGetSymbolAddress((void**)&wo,  h_wo);

    static int smem_set = 0;
    if (!smem_set) {
        cudaFuncSetAttribute(attn_tc, cudaFuncAttributeMaxDynamicSharedMemorySize,
                             ATTN_SMEM_BYTES);
        cudaFuncSetAttribute(gemm_fp16<0>, cudaFuncAttributeMaxDynamicSharedMemorySize,
                             GH_SMEM);
        cudaFuncSetAttribute(gemm_fp16<1>, cudaFuncAttributeMaxDynamicSharedMemorySize,
                             GH_SMEM);
        cudaFuncSetAttribute(gemm_fp16<2>, cudaFuncAttributeMaxDynamicSharedMemorySize,
                             GH_SMEM);
        smem_set = 1;
    }

    {
        int n4;
        n4 = (DHID * DIMF) / 4;
        round_half_kernel<<<(n4 + 255) / 256, 256>>>((const float4*)Wq,  (__half2*)wq,  n4);
        n4 = (2 * DHID * DIMF) / 4;
        round_half_kernel<<<(n4 + 255) / 256, 256>>>((const float4*)Wkv, (__half2*)wkv, n4);
        n4 = (DIMF * DHID) / 4;
        round_half_kernel<<<(n4 + 255) / 256, 256>>>((const float4*)Wo,  (__half2*)wo,  n4);
    }

    rmsnorm_kernel<<<BATCH * SEQ_N, 256>>>(x, gamma, xn);
    rmsnorm_kernel<<<BATCH * ROUTES * SEQ_K, 256>>>(ctx, gamma, cn);

    // Q projection: 4096 x 1024 x 2048
    gemm_fp16<0><<<dim3(DHID / 128, (BATCH * SEQ_N) / 128, 1), 256, GH_SMEM>>>(sq, nullptr);
    // KV projection: 8 x (1024 x 1024 x 2048)
    gemm_fp16<1><<<dim3(DHID / 128, SEQ_K / 128, BATCH * ROUTES), 256, GH_SMEM>>>(skv, nullptr);

    attn_tc<<<dim3(SEQ_N / 128, BATCH * NHEAD), 256, ATTN_SMEM_BYTES>>>(nullkv);

    // O projection: 4096 x 2048 x 1024
    gemm_fp16<2><<<dim3(DIMF / 128, (BATCH * SEQ_N) / 128, 1), 256, GH_SMEM>>>(nullptr, out);
}

// round 6
// speedup vs baseline: 7.1968x; 1.2843x over previous
#include <cuda_runtime.h>
#include <cuda_fp16.h>
#include <math.h>
#include <stdint.h>

#define BATCH 4
#define SEQ_N 1024
#define SEQ_K 1024
#define DIMF  2048
#define NHEAD 16
#define DHEAD 64
#define ROUTES 2
#define HPR   (NHEAD/ROUTES)
#define DHID  (NHEAD*DHEAD)   // 1024

// ---------------- scratch (static device allocations) ----------------
__device__ __half h_xn[(size_t)BATCH*SEQ_N*DIMF];          // normed x (fp16)
__device__ __half h_cn[(size_t)BATCH*ROUTES*SEQ_K*DIMF];   // normed context (fp16)
__device__ __half h_q [(size_t)BATCH*NHEAD*SEQ_N*DHEAD];   // fp16, scaled score_q/8
__device__ __half h_k [(size_t)BATCH*NHEAD*SEQ_K*DHEAD];   // fp16, scaled score_kv
__device__ __half h_v [(size_t)BATCH*NHEAD*SEQ_K*DHEAD];   // fp16, scaled score_kv
__device__ __half h_ao[(size_t)BATCH*SEQ_N*DHID];          // attn out (fp16)
__device__ __half h_wq [(size_t)DHID*DIMF];                // fp16 weights
__device__ __half h_wkv[(size_t)2*DHID*DIMF];
__device__ __half h_wo [(size_t)DIMF*DHID];

// ---------------- helpers ----------------
__device__ __forceinline__ void cp16(void* dst_smem, const void* src) {
    uint32_t d = (uint32_t)__cvta_generic_to_shared(dst_smem);
    asm volatile("cp.async.cg.shared.global [%0], [%1], 16;" :: "r"(d), "l"(src));
}
__device__ __forceinline__ void mma16h(float* c, const uint32_t* a, uint32_t b0, uint32_t b1) {
    asm volatile("mma.sync.aligned.m16n8k16.row.col.f32.f16.f16.f32 "
        "{%0,%1,%2,%3},{%4,%5,%6,%7},{%8,%9},{%0,%1,%2,%3};"
        : "+f"(c[0]), "+f"(c[1]), "+f"(c[2]), "+f"(c[3])
        : "r"(a[0]), "r"(a[1]), "r"(a[2]), "r"(a[3]), "r"(b0), "r"(b1));
}
__device__ __forceinline__ void ldsm4(uint32_t* r, uint32_t addr) {
    asm volatile("ldmatrix.sync.aligned.m8n8.x4.shared.b16 {%0,%1,%2,%3}, [%4];"
        : "=r"(r[0]), "=r"(r[1]), "=r"(r[2]), "=r"(r[3]) : "r"(addr));
}
__device__ __forceinline__ void ldsm4t(uint32_t* r, uint32_t addr) {
    asm volatile("ldmatrix.sync.aligned.m8n8.x4.trans.shared.b16 {%0,%1,%2,%3}, [%4];"
        : "=r"(r[0]), "=r"(r[1]), "=r"(r[2]), "=r"(r[3]) : "r"(addr));
}
__device__ __forceinline__ uint32_t s2u(const void* p) {
    uint32_t a;
    asm("{ .reg .u64 t; cvta.to.shared.u64 t, %1; cvt.u32.u64 %0, t; }"
        : "=r"(a) : "l"(p));
    return a;
}

// ---------------- weight fp32 -> fp16 prep ----------------
__global__ void __launch_bounds__(256) round_half_kernel(
    const float4* __restrict__ in, __half2* __restrict__ out, int n4)
{
    int i = blockIdx.x * 256 + threadIdx.x;
    if (i < n4) {
        float4 v = in[i];
        out[2 * i]     = __floats2half2_rn(v.x, v.y);
        out[2 * i + 1] = __floats2half2_rn(v.z, v.w);
    }
}

// ---------------- RMS norm (fp16 output) ----------------
__global__ void __launch_bounds__(256) rmsnorm_kernel(
    const float* __restrict__ in, const float* __restrict__ gamma,
    __half* __restrict__ out)
{
    const long row = blockIdx.x;
    const float4* xr = (const float4*)(in + row * (long)DIMF);
    const float4* g4 = (const float4*)gamma;
    const int t = threadIdx.x;

    float4 v0 = xr[2 * t];
    float4 v1 = xr[2 * t + 1];
    float ss = v0.x*v0.x + v0.y*v0.y + v0.z*v0.z + v0.w*v0.w
             + v1.x*v1.x + v1.y*v1.y + v1.z*v1.z + v1.w*v1.w;
    #pragma unroll
    for (int o = 16; o; o >>= 1) ss += __shfl_xor_sync(0xffffffffu, ss, o);
    __shared__ float red[8];
    if ((t & 31) == 0) red[t >> 5] = ss;
    __syncthreads();
    float tot = 0.f;
    #pragma unroll
    for (int i = 0; i < 8; i++) tot += red[i];
    const float s = sqrtf((float)DIMF) / fmaxf(sqrtf(tot), 1e-12f);

    float4 ga = g4[2 * t], gb = g4[2 * t + 1];
    __half2 o0 = __floats2half2_rn(v0.x*s*ga.x, v0.y*s*ga.y);
    __half2 o1 = __floats2half2_rn(v0.z*s*ga.z, v0.w*s*ga.w);
    __half2 o2 = __floats2half2_rn(v1.x*s*gb.x, v1.y*s*gb.y);
    __half2 o3 = __floats2half2_rn(v1.z*s*gb.z, v1.w*s*gb.w);
    uint4 pk;
    pk.x = *(uint32_t*)&o0; pk.y = *(uint32_t*)&o1;
    pk.z = *(uint32_t*)&o2; pk.w = *(uint32_t*)&o3;
    ((uint4*)(out + row * (long)DIMF))[t] = pk;
}

// ---------------- fp16 tensor-core GEMM, C(M,N) = A(M,K) * B(N,K)^T ----------------
// CTA tile 128x256, BK=64 halves (128B rows), 3-stage cp.async (144KB smem),
// 256 threads (8 warps 2x4), warp tile 64x64, ldmatrix fragment loads.
// swizzle: 16B group g of row r stored at group (g ^ (r&7)).
#define GH_STAGE 49152
#define GH_SMEM  (3 * GH_STAGE)

template <int MODE>
__global__ void __launch_bounds__(256, 1) gemm_fp16(
    const float* __restrict__ sc, float* __restrict__ out)
{
    constexpr int K  = (MODE == 2) ? DHID : DIMF;
    constexpr int NC = K / 64;

    extern __shared__ char smem[];
    const uint32_t smu = s2u(smem);

    const int bm = blockIdx.y, bn = blockIdx.x, bz = blockIdx.z;
    const int tid = threadIdx.x;
    const int lane = tid & 31, warp = tid >> 5;
    const int wm = warp >> 2, wn = warp & 3;
    const int g = lane >> 2, cq = lane & 3;

    const __half *A, *Bp;
    if (MODE == 0)      { A = h_xn + (size_t)bm * 128 * K;                        Bp = h_wq; }
    else if (MODE == 1) { A = h_cn + ((size_t)bz * SEQ_K + (size_t)bm * 128) * K;
                          Bp = h_wkv + (size_t)(bz & 1) * DHID * K; }
    else                { A = h_ao + (size_t)bm * 128 * K;                        Bp = h_wo; }
    Bp += (size_t)bn * 256 * K;

    // loader: A 128 rows x 128B, B 256 rows x 128B per chunk
    const int lr = tid >> 3, lg = tid & 7;
    const int lsw = (lg ^ (lr & 7)) << 4;
    auto load_chunk = [&](int c, int st) {
        char* aB = smem + st * GH_STAGE;
        char* bB = aB + 16384;
        const size_t ko = (size_t)c * 64 + lg * 8;
        #pragma unroll
        for (int t4 = 0; t4 < 4; t4++)
            cp16(aB + (lr + t4 * 32) * 128 + lsw, A + (size_t)(lr + t4 * 32) * K + ko);
        #pragma unroll
        for (int t4 = 0; t4 < 8; t4++)
            cp16(bB + (lr + t4 * 32) * 128 + lsw, Bp + (size_t)(lr + t4 * 32) * K + ko);
    };

    const int lrow = lane & 15, hi = lane >> 4;
    const int sw = lane & 7;                       // row&7 for all fragment rows
    int moff[4], noff[4];
    #pragma unroll
    for (int mt = 0; mt < 4; mt++) moff[mt] = (wm * 64 + mt * 16 + lrow) * 128;
    #pragma unroll
    for (int p = 0; p < 4; p++)    noff[p]  = (wn * 64 + p * 16 + lrow) * 128 + 16384;

    float c[4][8][4];
    #pragma unroll
    for (int mt = 0; mt < 4; mt++)
        #pragma unroll
        for (int nt = 0; nt < 8; nt++)
            #pragma unroll
            for (int i = 0; i < 4; i++) c[mt][nt][i] = 0.f;

    load_chunk(0, 0);
    asm volatile("cp.async.commit_group;");
    load_chunk(1, 1);
    asm volatile("cp.async.commit_group;");

    #pragma unroll 1
    for (int t = 0; t < NC; t++) {
        asm volatile("cp.async.wait_group 1;");
        __syncthreads();

        if (t + 2 < NC) load_chunk(t + 2, (t + 2) % 3);
        asm volatile("cp.async.commit_group;");

        const uint32_t sb = smu + (t % 3) * GH_STAGE;

        #pragma unroll
        for (int ks = 0; ks < 4; ks++) {
            const int koff = ((2 * ks + hi) ^ sw) << 4;
            uint32_t af[4][4], bf[4][4];
            #pragma unroll
            for (int mt = 0; mt < 4; mt++) ldsm4(af[mt], sb + moff[mt] + koff);
            #pragma unroll
            for (int p = 0; p < 4; p++)    ldsm4(bf[p], sb + noff[p] + koff);
            #pragma unroll
            for (int mt = 0; mt < 4; mt++)
                #pragma unroll
                for (int nt = 0; nt < 8; nt++)
                    mma16h(c[mt][nt], af[mt], bf[nt >> 1][nt & 1], bf[nt >> 1][(nt & 1) + 2]);
        }
        __syncthreads();
    }

    // ---- epilogue ----
    #pragma unroll
    for (int mt = 0; mt < 4; mt++) {
        #pragma unroll
        for (int i = 0; i < 2; i++) {
            const int m = bm * 128 + wm * 64 + mt * 16 + g + i * 8;
            float srow = 0.f;
            if (MODE == 0) srow = sc[m] * 0.125f;
            if (MODE == 1) srow = sc[(size_t)bz * SEQ_K + m];
            #pragma unroll
            for (int nt = 0; nt < 8; nt++) {
                const int o = bn * 256 + wn * 64 + (nt >> 1) * 16 + (nt & 1) * 8 + 2 * cq;
                float v0 = c[mt][nt][i * 2 + 0];
                float v1 = c[mt][nt][i * 2 + 1];
                if (MODE == 0) {
                    int b = m >> 10, nn = m & 1023;
                    int h = o >> 6,  d  = o & 63;
                    *(__half2*)&h_q[(((size_t)(b * NHEAD + h)) * SEQ_N + nn) * DHEAD + d] =
                        __floats2half2_rn(v0 * srow, v1 * srow);
                } else if (MODE == 1) {
                    int hp = o >> 7, dd = o & 127;
                    int b = bz >> 1, rt = bz & 1;
                    size_t base = (((size_t)(b * NHEAD + rt * HPR + hp)) * SEQ_K + m) * DHEAD;
                    __half2 hv = __floats2half2_rn(v0 * srow, v1 * srow);
                    if (dd < DHEAD) *(__half2*)&h_k[base + dd]         = hv;
                    else            *(__half2*)&h_v[base + dd - DHEAD] = hv;
                } else {
                    *(float2*)&out[(size_t)m * DIMF + o] = make_float2(v0, v1);
                }
            }
        }
    }
}

// ---------------- fp16 tensor-core flash attention ----------------
// grid (SEQ_N/128, BATCH*NHEAD), 256 threads = 8 warps, 16 q-rows per warp.
// smem (halves, all tiles row=128B with 16B-group XOR swizzle g^(r&7)):
//   qs [128][64] @0, ps [128][64] @8192, ks 2x[64][64] @16384, vs 2x[64][64] @24576
//   nk/nv float[64] each @ byte 65536
#define AT_SMEM 66048

__global__ void __launch_bounds__(256, 2) attn_fp16(const float* __restrict__ nullkv)
{
    extern __shared__ __half sh[];
    __half* qs = sh;
    __half* ps = sh + 8192;
    __half* ks = sh + 16384;
    __half* vs = sh + 24576;
    float* nk = (float*)(sh + 32768);
    float* nv = nk + 64;
    const uint32_t smu = s2u(sh);

    const int bh = blockIdx.y, h = bh & (NHEAD - 1);
    const int qbase = blockIdx.x * 128;
    const int tid = threadIdx.x, lane = tid & 31, w = tid >> 5;
    const int g = lane >> 2, cq = lane & 3;
    const int lrow = lane & 15, hi = lane >> 4;
    const int sw = lane & 7;

    const __half* qg = h_q + ((size_t)bh * SEQ_N + qbase) * DHEAD;
    const __half* kgp = h_k + (size_t)bh * SEQ_K * DHEAD;
    const __half* vgp = h_v + (size_t)bh * SEQ_K * DHEAD;

    // load Q (1024 x 16B chunks)
    #pragma unroll
    for (int i = 0; i < 4; i++) {
        int idx = tid + i * 256;
        int r = idx >> 3, gg = idx & 7;
        cp16(qs + r * 64 + ((gg ^ (r & 7)) << 3), qg + (size_t)r * DHEAD + gg * 8);
    }
    if (tid < 64)       nk[tid]      = nullkv[h * DHEAD + tid];
    else if (tid < 128) nv[tid - 64] = nullkv[NHEAD * DHEAD + h * DHEAD + (tid - 64)];

    auto load_kv = [&](int tile, int buf) {
        const __half* kt = kgp + (size_t)tile * 64 * DHEAD;
        const __half* vt = vgp + (size_t)tile * 64 * DHEAD;
        __half* kd = ks + buf * 4096;
        __half* vd = vs + buf * 4096;
        #pragma unroll
        for (int i = 0; i < 2; i++) {
            int idx = tid + i * 256;            // 0..511
            int r = idx >> 3, gg = idx & 7;
            int off = r * 64 + ((gg ^ (r & 7)) << 3);
            cp16(kd + off, kt + (size_t)r * DHEAD + gg * 8);
            cp16(vd + off, vt + (size_t)r * DHEAD + gg * 8);
        }
    };
    load_kv(0, 0);
    asm volatile("cp.async.commit_group;");
    __syncthreads();    // qs visible for null-init? (cp.async not yet — wait below)

    asm volatile("cp.async.wait_group 0;");
    __syncthreads();

    // null-key init (q fp16 from swizzled smem, math fp32)
    float m0, m1, l0 = 1.f, l1 = 1.f;
    {
        int row = w * 16 + lrow;
        int halfo = hi * 32;
        float s = 0.f;
        #pragma unroll
        for (int d = 0; d < 32; d++) {
            int cidx = halfo + d;
            int gg = cidx >> 3;
            float qv = __half2float(qs[row * 64 + ((gg ^ (row & 7)) << 3) + (cidx & 7)]);
            s += qv * nk[cidx];
        }
        s += __shfl_xor_sync(0xffffffffu, s, 16);
        m0 = __shfl_sync(0xffffffffu, s, g);
        m1 = __shfl_sync(0xffffffffu, s, g + 8);
    }
    float o[8][4];
    #pragma unroll
    for (int nt = 0; nt < 8; nt++) {
        float va = nv[nt * 8 + 2 * cq], vb = nv[nt * 8 + 2 * cq + 1];
        o[nt][0] = va; o[nt][1] = vb; o[nt][2] = va; o[nt][3] = vb;
    }

    const uint32_t aqbase = smu + (w * 16 + lrow) * 128;
    const uint32_t apbase = aqbase + 16384;
    __half* psw = ps + (w * 16) * 64;

    #pragma unroll 1
    for (int t = 0; t < 16; t++) {
        if (t > 0) {
            asm volatile("cp.async.wait_group 0;");
            __syncthreads();
        }
        if (t + 1 < 16) load_kv(t + 1, (t + 1) & 1);
        asm volatile("cp.async.commit_group;");

        const uint32_t kbB = smu + 32768 + (t & 1) * 8192 + lrow * 128;
        const uint32_t vbB = smu + 49152 + (t & 1) * 8192 + lrow * 128;

        // S = Q K^T
        float s[8][4];
        #pragma unroll
        for (int nt = 0; nt < 8; nt++)
            s[nt][0] = s[nt][1] = s[nt][2] = s[nt][3] = 0.f;

        #pragma unroll
        for (int kst = 0; kst < 4; kst++) {
            const int koff = ((2 * kst + hi) ^ sw) << 4;
            uint32_t af[4], bf[4][4];
            ldsm4(af, aqbase + koff);
            #pragma unroll
            for (int p = 0; p < 4; p++) ldsm4(bf[p], kbB + p * 2048 + koff);
            #pragma unroll
            for (int nt = 0; nt < 8; nt++)
                mma16h(s[nt], af, bf[nt >> 1][nt & 1], bf[nt >> 1][(nt & 1) + 2]);
        }

        // online softmax
        float mx0 = -1e30f, mx1 = -1e30f;
        #pragma unroll
        for (int nt = 0; nt < 8; nt++) {
            mx0 = fmaxf(mx0, fmaxf(s[nt][0], s[nt][1]));
            mx1 = fmaxf(mx1, fmaxf(s[nt][2], s[nt][3]));
        }
        mx0 = fmaxf(mx0, __shfl_xor_sync(0xffffffffu, mx0, 1));
        mx0 = fmaxf(mx0, __shfl_xor_sync(0xffffffffu, mx0, 2));
        mx1 = fmaxf(mx1, __shfl_xor_sync(0xffffffffu, mx1, 1));
        mx1 = fmaxf(mx1, __shfl_xor_sync(0xffffffffu, mx1, 2));
        float mn0 = fmaxf(m0, mx0), mn1 = fmaxf(m1, mx1);
        float c0 = __expf(m0 - mn0), c1 = __expf(m1 - mn1);
        float p0 = 0.f, p1 = 0.f;
        #pragma unroll
        for (int nt = 0; nt < 8; nt++) {
            s[nt][0] = __expf(s[nt][0] - mn0);
            s[nt][1] = __expf(s[nt][1] - mn0);
            s[nt][2] = __expf(s[nt][2] - mn1);
            s[nt][3] = __expf(s[nt][3] - mn1);
            p0 += s[nt][0] + s[nt][1];
            p1 += s[nt][2] + s[nt][3];
        }
        p0 += __shfl_xor_sync(0xffffffffu, p0, 1);
        p0 += __shfl_xor_sync(0xffffffffu, p0, 2);
        p1 += __shfl_xor_sync(0xffffffffu, p1, 1);
        p1 += __shfl_xor_sync(0xffffffffu, p1, 2);
        l0 = l0 * c0 + p0; l1 = l1 * c1 + p1;
        m0 = mn0; m1 = mn1;
        #pragma unroll
        for (int nt = 0; nt < 8; nt++) {
            o[nt][0] *= c0; o[nt][1] *= c0;
            o[nt][2] *= c1; o[nt][3] *= c1;
        }

        // write P (fp16) to warp-private swizzled strip
        #pragma unroll
        for (int nt = 0; nt < 8; nt++) {
            *(__half2*)(psw + g * 64 + ((nt ^ g) << 3) + 2 * cq) =
                __floats2half2_rn(s[nt][0], s[nt][1]);
            *(__half2*)(psw + (g + 8) * 64 + ((nt ^ g) << 3) + 2 * cq) =
                __floats2half2_rn(s[nt][2], s[nt][3]);
        }
        __syncwarp();

        // O += P V   (V via ldmatrix.trans from [key][dim])
        #pragma unroll
        for (int kst = 0; kst < 4; kst++) {
            const int koff = ((2 * kst + hi) ^ sw) << 4;
            uint32_t ap[4];
            ldsm4(ap, apbase + koff);
            #pragma unroll
            for (int nt2 = 0; nt2 < 4; nt2++) {
                const int voff = ((nt2 * 2 + hi) ^ sw) << 4;
                uint32_t tv[4];
                ldsm4t(tv, vbB + kst * 2048 + voff);
                mma16h(o[2 * nt2],     ap, tv[0], tv[1]);
                mma16h(o[2 * nt2 + 1], ap, tv[2], tv[3]);
            }
        }
    }

    const int b = bh >> 4;
    const float i0 = 1.f / l0, i1 = 1.f / l1;
    const int n0 = qbase + w * 16 + g;
    const size_t base0 = ((size_t)(b * SEQ_N + n0)) * DHID + h * DHEAD;
    const size_t base1 = ((size_t)(b * SEQ_N + n0 + 8)) * DHID + h * DHEAD;
    #pragma unroll
    for (int nt = 0; nt < 8; nt++) {
        int col = nt * 8 + 2 * cq;
        *(__half2*)&h_ao[base0 + col] = __floats2half2_rn(o[nt][0] * i0, o[nt][1] * i0);
        *(__half2*)&h_ao[base1 + col] = __floats2half2_rn(o[nt][2] * i1, o[nt][3] * i1);
    }
}

// ---------------- launch ----------------
extern "C" void kernel_launch(void* const* d_in, const int* in_sizes, int n_in,
                              void* d_out, int out_size)
{
    const float* x      = (const float*)d_in[0];
    const float* ctx    = (const float*)d_in[1];
    const float* skv    = (const float*)d_in[2];
    const float* sq     = (const float*)d_in[3];
    const float* gamma  = (const float*)d_in[4];
    const float* nullkv = (const float*)d_in[5];
    const float* Wq     = (const float*)d_in[6];
    const float* Wkv    = (const float*)d_in[7];
    const float* Wo     = (const float*)d_in[8];
    float* out = (float*)d_out;

    __half* xn;  cudaGetSymbolAddress((void**)&xn,  h_xn);
    __half* cn;  cudaGetSymbolAddress((void**)&cn,  h_cn);
    __half* wq;  cudaGetSymbolAddress((void**)&wq,  h_wq);
    __half* wkv; cudaGetSymbolAddress((void**)&wkv, h_wkv);
    __half* wo;  cudaGetSymbolAddress((void**)&wo,  h_wo);

    static int smem_set = 0;
    if (!smem_set) {
        cudaFuncSetAttribute(attn_fp16, cudaFuncAttributeMaxDynamicSharedMemorySize,
                             AT_SMEM);
        cudaFuncSetAttribute(gemm_fp16<0>, cudaFuncAttributeMaxDynamicSharedMemorySize,
                             GH_SMEM);
        cudaFuncSetAttribute(gemm_fp16<1>, cudaFuncAttributeMaxDynamicSharedMemorySize,
                             GH_SMEM);
        cudaFuncSetAttribute(gemm_fp16<2>, cudaFuncAttributeMaxDynamicSharedMemorySize,
                             GH_SMEM);
        smem_set = 1;
    }

    {
        int n4;
        n4 = (DHID * DIMF) / 4;
        round_half_kernel<<<(n4 + 255) / 256, 256>>>((const float4*)Wq,  (__half2*)wq,  n4);
        n4 = (2 * DHID * DIMF) / 4;
        round_half_kernel<<<(n4 + 255) / 256, 256>>>((const float4*)Wkv, (__half2*)wkv, n4);
        n4 = (DIMF * DHID) / 4;
        round_half_kernel<<<(n4 + 255) / 256, 256>>>((const float4*)Wo,  (__half2*)wo,  n4);
    }

    rmsnorm_kernel<<<BATCH * SEQ_N, 256>>>(x, gamma, xn);
    rmsnorm_kernel<<<BATCH * ROUTES * SEQ_K, 256>>>(ctx, gamma, cn);

    // Q projection: 4096 x 1024 x 2048
    gemm_fp16<0><<<dim3(DHID / 256, (BATCH * SEQ_N) / 128, 1), 256, GH_SMEM>>>(sq, nullptr);
    // KV projection: 8 x (1024 x 1024 x 2048)
    gemm_fp16<1><<<dim3(DHID / 256, SEQ_K / 128, BATCH * ROUTES), 256, GH_SMEM>>>(skv, nullptr);

    attn_fp16<<<dim3(SEQ_N / 128, BATCH * NHEAD), 256, AT_SMEM>>>(nullkv);

    // O projection: 4096 x 2048 x 1024
    gemm_fp16<2><<<dim3(DIMF / 256, (BATCH * SEQ_N) / 128, 1), 256, GH_SMEM>>>(nullptr, out);
}

// round 7
// speedup vs baseline: 7.3996x; 1.0282x over previous
#include <cuda_runtime.h>
#include <cuda_fp16.h>
#include <math.h>
#include <stdint.h>

#define BATCH 4
#define SEQ_N 1024
#define SEQ_K 1024
#define DIMF  2048
#define NHEAD 16
#define DHEAD 64
#define ROUTES 2
#define HPR   (NHEAD/ROUTES)
#define DHID  (NHEAD*DHEAD)   // 1024

// ---------------- scratch (static device allocations) ----------------
__device__ __half h_xn[(size_t)BATCH*SEQ_N*DIMF];          // normed x (fp16)
__device__ __half h_cn[(size_t)BATCH*ROUTES*SEQ_K*DIMF];   // normed context (fp16)
__device__ __half h_q [(size_t)BATCH*NHEAD*SEQ_N*DHEAD];   // fp16, scaled score_q/8
__device__ __half h_k [(size_t)BATCH*NHEAD*SEQ_K*DHEAD];   // fp16, scaled score_kv
__device__ __half h_v [(size_t)BATCH*NHEAD*SEQ_K*DHEAD];   // fp16, scaled score_kv
__device__ __half h_ao[(size_t)BATCH*SEQ_N*DHID];          // attn out (fp16)
__device__ __half h_wq [(size_t)DHID*DIMF];                // fp16 weights
__device__ __half h_wkv[(size_t)2*DHID*DIMF];
__device__ __half h_wo [(size_t)DIMF*DHID];

// ---------------- helpers ----------------
__device__ __forceinline__ void cp16(void* dst_smem, const void* src) {
    uint32_t d = (uint32_t)__cvta_generic_to_shared(dst_smem);
    asm volatile("cp.async.cg.shared.global [%0], [%1], 16;" :: "r"(d), "l"(src));
}
__device__ __forceinline__ void mma16h(float* c, const uint32_t* a, uint32_t b0, uint32_t b1) {
    asm volatile("mma.sync.aligned.m16n8k16.row.col.f32.f16.f16.f32 "
        "{%0,%1,%2,%3},{%4,%5,%6,%7},{%8,%9},{%0,%1,%2,%3};"
        : "+f"(c[0]), "+f"(c[1]), "+f"(c[2]), "+f"(c[3])
        : "r"(a[0]), "r"(a[1]), "r"(a[2]), "r"(a[3]), "r"(b0), "r"(b1));
}
__device__ __forceinline__ void ldsm4(uint32_t* r, uint32_t addr) {
    asm volatile("ldmatrix.sync.aligned.m8n8.x4.shared.b16 {%0,%1,%2,%3}, [%4];"
        : "=r"(r[0]), "=r"(r[1]), "=r"(r[2]), "=r"(r[3]) : "r"(addr));
}
__device__ __forceinline__ void ldsm4t(uint32_t* r, uint32_t addr) {
    asm volatile("ldmatrix.sync.aligned.m8n8.x4.trans.shared.b16 {%0,%1,%2,%3}, [%4];"
        : "=r"(r[0]), "=r"(r[1]), "=r"(r[2]), "=r"(r[3]) : "r"(addr));
}
__device__ __forceinline__ uint32_t s2u(const void* p) {
    uint32_t a;
    asm("{ .reg .u64 t; cvta.to.shared.u64 t, %1; cvt.u32.u64 %0, t; }"
        : "=r"(a) : "l"(p));
    return a;
}

// ---------------- merged weight fp32 -> fp16 prep ----------------
#define WQ_N4  ((DHID * DIMF) / 4)            // 524288
#define WKV_N4 ((2 * DHID * DIMF) / 4)        // 1048576
#define WO_N4  ((DIMF * DHID) / 4)            // 524288
#define W_TOTAL_N4 (WQ_N4 + WKV_N4 + WO_N4)

__global__ void __launch_bounds__(256) prep_weights_kernel(
    const float4* __restrict__ Wq, const float4* __restrict__ Wkv,
    const float4* __restrict__ Wo)
{
    int i = blockIdx.x * 256 + threadIdx.x;
    if (i >= W_TOTAL_N4) return;
    const float4* src;
    __half2* dst;
    int j = i;
    if (j < WQ_N4)                { src = Wq;  dst = (__half2*)h_wq; }
    else if ((j -= WQ_N4) < WKV_N4) { src = Wkv; dst = (__half2*)h_wkv; }
    else { j -= WKV_N4;             src = Wo;  dst = (__half2*)h_wo; }
    float4 v = src[j];
    dst[2 * j]     = __floats2half2_rn(v.x, v.y);
    dst[2 * j + 1] = __floats2half2_rn(v.z, v.w);
}

// ---------------- merged RMS norm (x rows then context rows) ----------------
__global__ void __launch_bounds__(256) rmsnorm_kernel(
    const float* __restrict__ x, const float* __restrict__ ctx,
    const float* __restrict__ gamma)
{
    const long row = blockIdx.x;
    const float* in;
    __half* out;
    if (row < BATCH * SEQ_N) {
        in  = x + row * (long)DIMF;
        out = h_xn + row * (long)DIMF;
    } else {
        long r = row - BATCH * SEQ_N;
        in  = ctx + r * (long)DIMF;
        out = h_cn + r * (long)DIMF;
    }
    const float4* xr = (const float4*)in;
    const float4* g4 = (const float4*)gamma;
    const int t = threadIdx.x;

    float4 v0 = xr[2 * t];
    float4 v1 = xr[2 * t + 1];
    float ss = v0.x*v0.x + v0.y*v0.y + v0.z*v0.z + v0.w*v0.w
             + v1.x*v1.x + v1.y*v1.y + v1.z*v1.z + v1.w*v1.w;
    #pragma unroll
    for (int o = 16; o; o >>= 1) ss += __shfl_xor_sync(0xffffffffu, ss, o);
    __shared__ float red[8];
    if ((t & 31) == 0) red[t >> 5] = ss;
    __syncthreads();
    float tot = 0.f;
    #pragma unroll
    for (int i = 0; i < 8; i++) tot += red[i];
    const float s = sqrtf((float)DIMF) / fmaxf(sqrtf(tot), 1e-12f);

    float4 ga = g4[2 * t], gb = g4[2 * t + 1];
    __half2 o0 = __floats2half2_rn(v0.x*s*ga.x, v0.y*s*ga.y);
    __half2 o1 = __floats2half2_rn(v0.z*s*ga.z, v0.w*s*ga.w);
    __half2 o2 = __floats2half2_rn(v1.x*s*gb.x, v1.y*s*gb.y);
    __half2 o3 = __floats2half2_rn(v1.z*s*gb.z, v1.w*s*gb.w);
    uint4 pk;
    pk.x = *(uint32_t*)&o0; pk.y = *(uint32_t*)&o1;
    pk.z = *(uint32_t*)&o2; pk.w = *(uint32_t*)&o3;
    ((uint4*)out)[t] = pk;
}

// ---------------- fp16 tensor-core GEMM core ----------------
// CTA tile 128x256, BK=64 halves (128B rows), 3-stage cp.async (144KB smem),
// 256 threads (8 warps 2x4), warp tile 64x64, ldmatrix fragment loads.
// swizzle: 16B group g of row r stored at group (g ^ (r&7)).
#define GH_STAGE 49152
#define GH_SMEM  (3 * GH_STAGE)

// ---- merged Q + KV projection (K = 2048) ----
// grid.x = 384: blocks [0,128) -> Q proj tiles, [128,384) -> KV proj tiles.
__global__ void __launch_bounds__(256, 1) gemm_qkv(
    const float* __restrict__ sq, const float* __restrict__ skv)
{
    constexpr int K  = DIMF;
    constexpr int NC = K / 64;

    extern __shared__ char smem[];
    const uint32_t smu = s2u(smem);

    const int id = blockIdx.x;
    const bool isQ = (id < 128);
    int bm, bn, bz = 0;
    const __half *A, *Bp;
    if (isQ) {
        bm = id >> 2; bn = id & 3;
        A  = h_xn + (size_t)bm * 128 * K;
        Bp = h_wq + (size_t)bn * 256 * K;
    } else {
        int r = id - 128;
        bz = r >> 5;
        int rr = r & 31;
        bm = rr >> 2; bn = rr & 3;
        A  = h_cn + ((size_t)bz * SEQ_K + (size_t)bm * 128) * K;
        Bp = h_wkv + (size_t)(bz & 1) * DHID * K + (size_t)bn * 256 * K;
    }

    const int tid = threadIdx.x;
    const int lane = tid & 31, warp = tid >> 5;
    const int wm = warp >> 2, wn = warp & 3;
    const int g = lane >> 2, cq = lane & 3;

    const int lr = tid >> 3, lg = tid & 7;
    const int lsw = (lg ^ (lr & 7)) << 4;
    auto load_chunk = [&](int c, int st) {
        char* aB = smem + st * GH_STAGE;
        char* bB = aB + 16384;
        const size_t ko = (size_t)c * 64 + lg * 8;
        #pragma unroll
        for (int t4 = 0; t4 < 4; t4++)
            cp16(aB + (lr + t4 * 32) * 128 + lsw, A + (size_t)(lr + t4 * 32) * K + ko);
        #pragma unroll
        for (int t4 = 0; t4 < 8; t4++)
            cp16(bB + (lr + t4 * 32) * 128 + lsw, Bp + (size_t)(lr + t4 * 32) * K + ko);
    };

    const int lrow = lane & 15, hi = lane >> 4;
    const int sw = lane & 7;
    int moff[4], noff[4];
    #pragma unroll
    for (int mt = 0; mt < 4; mt++) moff[mt] = (wm * 64 + mt * 16 + lrow) * 128;
    #pragma unroll
    for (int p = 0; p < 4; p++)    noff[p]  = (wn * 64 + p * 16 + lrow) * 128 + 16384;

    float c[4][8][4];
    #pragma unroll
    for (int mt = 0; mt < 4; mt++)
        #pragma unroll
        for (int nt = 0; nt < 8; nt++)
            #pragma unroll
            for (int i = 0; i < 4; i++) c[mt][nt][i] = 0.f;

    load_chunk(0, 0);
    asm volatile("cp.async.commit_group;");
    load_chunk(1, 1);
    asm volatile("cp.async.commit_group;");

    #pragma unroll 1
    for (int t = 0; t < NC; t++) {
        asm volatile("cp.async.wait_group 1;");
        __syncthreads();

        if (t + 2 < NC) load_chunk(t + 2, (t + 2) % 3);
        asm volatile("cp.async.commit_group;");

        const uint32_t sb = smu + (t % 3) * GH_STAGE;

        #pragma unroll
        for (int ks = 0; ks < 4; ks++) {
            const int koff = ((2 * ks + hi) ^ sw) << 4;
            uint32_t af[4][4], bf[4][4];
            #pragma unroll
            for (int mt = 0; mt < 4; mt++) ldsm4(af[mt], sb + moff[mt] + koff);
            #pragma unroll
            for (int p = 0; p < 4; p++)    ldsm4(bf[p], sb + noff[p] + koff);
            #pragma unroll
            for (int mt = 0; mt < 4; mt++)
                #pragma unroll
                for (int nt = 0; nt < 8; nt++)
                    mma16h(c[mt][nt], af[mt], bf[nt >> 1][nt & 1], bf[nt >> 1][(nt & 1) + 2]);
        }
        // NOTE: no trailing __syncthreads — the next iteration's top barrier
        // orders these reads against the buffer overwrite two chunks ahead.
    }

    // ---- epilogue ----
    #pragma unroll
    for (int mt = 0; mt < 4; mt++) {
        #pragma unroll
        for (int i = 0; i < 2; i++) {
            const int m = bm * 128 + wm * 64 + mt * 16 + g + i * 8;
            const float srow = isQ ? sq[m] * 0.125f : skv[(size_t)bz * SEQ_K + m];
            #pragma unroll
            for (int nt = 0; nt < 8; nt++) {
                const int o = bn * 256 + wn * 64 + (nt >> 1) * 16 + (nt & 1) * 8 + 2 * cq;
                float v0 = c[mt][nt][i * 2 + 0];
                float v1 = c[mt][nt][i * 2 + 1];
                __half2 hv = __floats2half2_rn(v0 * srow, v1 * srow);
                if (isQ) {
                    int b = m >> 10, nn = m & 1023;
                    int h = o >> 6,  d  = o & 63;
                    *(__half2*)&h_q[(((size_t)(b * NHEAD + h)) * SEQ_N + nn) * DHEAD + d] = hv;
                } else {
                    int hp = o >> 7, dd = o & 127;
                    int b = bz >> 1, rt = bz & 1;
                    size_t base = (((size_t)(b * NHEAD + rt * HPR + hp)) * SEQ_K + m) * DHEAD;
                    if (dd < DHEAD) *(__half2*)&h_k[base + dd]         = hv;
                    else            *(__half2*)&h_v[base + dd - DHEAD] = hv;
                }
            }
        }
    }
}

// ---- O projection (K = 1024) ----
__global__ void __launch_bounds__(256, 1) gemm_o(float* __restrict__ out)
{
    constexpr int K  = DHID;
    constexpr int NC = K / 64;

    extern __shared__ char smem[];
    const uint32_t smu = s2u(smem);

    const int bm = blockIdx.y, bn = blockIdx.x;
    const int tid = threadIdx.x;
    const int lane = tid & 31, warp = tid >> 5;
    const int wm = warp >> 2, wn = warp & 3;
    const int g = lane >> 2, cq = lane & 3;

    const __half* A  = h_ao + (size_t)bm * 128 * K;
    const __half* Bp = h_wo + (size_t)bn * 256 * K;

    const int lr = tid >> 3, lg = tid & 7;
    const int lsw = (lg ^ (lr & 7)) << 4;
    auto load_chunk = [&](int c, int st) {
        char* aB = smem + st * GH_STAGE;
        char* bB = aB + 16384;
        const size_t ko = (size_t)c * 64 + lg * 8;
        #pragma unroll
        for (int t4 = 0; t4 < 4; t4++)
            cp16(aB + (lr + t4 * 32) * 128 + lsw, A + (size_t)(lr + t4 * 32) * K + ko);
        #pragma unroll
        for (int t4 = 0; t4 < 8; t4++)
            cp16(bB + (lr + t4 * 32) * 128 + lsw, Bp + (size_t)(lr + t4 * 32) * K + ko);
    };

    const int lrow = lane & 15, hi = lane >> 4;
    const int sw = lane & 7;
    int moff[4], noff[4];
    #pragma unroll
    for (int mt = 0; mt < 4; mt++) moff[mt] = (wm * 64 + mt * 16 + lrow) * 128;
    #pragma unroll
    for (int p = 0; p < 4; p++)    noff[p]  = (wn * 64 + p * 16 + lrow) * 128 + 16384;

    float c[4][8][4];
    #pragma unroll
    for (int mt = 0; mt < 4; mt++)
        #pragma unroll
        for (int nt = 0; nt < 8; nt++)
            #pragma unroll
            for (int i = 0; i < 4; i++) c[mt][nt][i] = 0.f;

    load_chunk(0, 0);
    asm volatile("cp.async.commit_group;");
    load_chunk(1, 1);
    asm volatile("cp.async.commit_group;");

    #pragma unroll 1
    for (int t = 0; t < NC; t++) {
        asm volatile("cp.async.wait_group 1;");
        __syncthreads();

        if (t + 2 < NC) load_chunk(t + 2, (t + 2) % 3);
        asm volatile("cp.async.commit_group;");

        const uint32_t sb = smu + (t % 3) * GH_STAGE;

        #pragma unroll
        for (int ks = 0; ks < 4; ks++) {
            const int koff = ((2 * ks + hi) ^ sw) << 4;
            uint32_t af[4][4], bf[4][4];
            #pragma unroll
            for (int mt = 0; mt < 4; mt++) ldsm4(af[mt], sb + moff[mt] + koff);
            #pragma unroll
            for (int p = 0; p < 4; p++)    ldsm4(bf[p], sb + noff[p] + koff);
            #pragma unroll
            for (int mt = 0; mt < 4; mt++)
                #pragma unroll
                for (int nt = 0; nt < 8; nt++)
                    mma16h(c[mt][nt], af[mt], bf[nt >> 1][nt & 1], bf[nt >> 1][(nt & 1) + 2]);
        }
    }

    #pragma unroll
    for (int mt = 0; mt < 4; mt++) {
        #pragma unroll
        for (int i = 0; i < 2; i++) {
            const int m = bm * 128 + wm * 64 + mt * 16 + g + i * 8;
            #pragma unroll
            for (int nt = 0; nt < 8; nt++) {
                const int o = bn * 256 + wn * 64 + (nt >> 1) * 16 + (nt & 1) * 8 + 2 * cq;
                *(float2*)&out[(size_t)m * DIMF + o] =
                    make_float2(c[mt][nt][i * 2 + 0], c[mt][nt][i * 2 + 1]);
            }
        }
    }
}

// ---------------- fp16 tensor-core flash attention ----------------
#define AT_SMEM 66048

__global__ void __launch_bounds__(256, 2) attn_fp16(const float* __restrict__ nullkv)
{
    extern __shared__ __half sh[];
    __half* qs = sh;
    __half* ps = sh + 8192;
    __half* ks = sh + 16384;
    __half* vs = sh + 24576;
    float* nk = (float*)(sh + 32768);
    float* nv = nk + 64;
    const uint32_t smu = s2u(sh);

    const int bh = blockIdx.y, h = bh & (NHEAD - 1);
    const int qbase = blockIdx.x * 128;
    const int tid = threadIdx.x, lane = tid & 31, w = tid >> 5;
    const int g = lane >> 2, cq = lane & 3;
    const int lrow = lane & 15, hi = lane >> 4;
    const int sw = lane & 7;

    const __half* qg = h_q + ((size_t)bh * SEQ_N + qbase) * DHEAD;
    const __half* kgp = h_k + (size_t)bh * SEQ_K * DHEAD;
    const __half* vgp = h_v + (size_t)bh * SEQ_K * DHEAD;

    #pragma unroll
    for (int i = 0; i < 4; i++) {
        int idx = tid + i * 256;
        int r = idx >> 3, gg = idx & 7;
        cp16(qs + r * 64 + ((gg ^ (r & 7)) << 3), qg + (size_t)r * DHEAD + gg * 8);
    }
    if (tid < 64)       nk[tid]      = nullkv[h * DHEAD + tid];
    else if (tid < 128) nv[tid - 64] = nullkv[NHEAD * DHEAD + h * DHEAD + (tid - 64)];

    auto load_kv = [&](int tile, int buf) {
        const __half* kt = kgp + (size_t)tile * 64 * DHEAD;
        const __half* vt = vgp + (size_t)tile * 64 * DHEAD;
        __half* kd = ks + buf * 4096;
        __half* vd = vs + buf * 4096;
        #pragma unroll
        for (int i = 0; i < 2; i++) {
            int idx = tid + i * 256;
            int r = idx >> 3, gg = idx & 7;
            int off = r * 64 + ((gg ^ (r & 7)) << 3);
            cp16(kd + off, kt + (size_t)r * DHEAD + gg * 8);
            cp16(vd + off, vt + (size_t)r * DHEAD + gg * 8);
        }
    };
    load_kv(0, 0);
    asm volatile("cp.async.commit_group;");

    asm volatile("cp.async.wait_group 0;");
    __syncthreads();

    float m0, m1, l0 = 1.f, l1 = 1.f;
    {
        int row = w * 16 + lrow;
        int halfo = hi * 32;
        float s = 0.f;
        #pragma unroll
        for (int d = 0; d < 32; d++) {
            int cidx = halfo + d;
            int gg = cidx >> 3;
            float qv = __half2float(qs[row * 64 + ((gg ^ (row & 7)) << 3) + (cidx & 7)]);
            s += qv * nk[cidx];
        }
        s += __shfl_xor_sync(0xffffffffu, s, 16);
        m0 = __shfl_sync(0xffffffffu, s, g);
        m1 = __shfl_sync(0xffffffffu, s, g + 8);
    }
    float o[8][4];
    #pragma unroll
    for (int nt = 0; nt < 8; nt++) {
        float va = nv[nt * 8 + 2 * cq], vb = nv[nt * 8 + 2 * cq + 1];
        o[nt][0] = va; o[nt][1] = vb; o[nt][2] = va; o[nt][3] = vb;
    }

    const uint32_t aqbase = smu + (w * 16 + lrow) * 128;
    const uint32_t apbase = aqbase + 16384;
    __half* psw = ps + (w * 16) * 64;

    #pragma unroll 1
    for (int t = 0; t < 16; t++) {
        if (t > 0) {
            asm volatile("cp.async.wait_group 0;");
            __syncthreads();
        }
        if (t + 1 < 16) load_kv(t + 1, (t + 1) & 1);
        asm volatile("cp.async.commit_group;");

        const uint32_t kbB = smu + 32768 + (t & 1) * 8192 + lrow * 128;
        const uint32_t vbB = smu + 49152 + (t & 1) * 8192 + lrow * 128;

        float s[8][4];
        #pragma unroll
        for (int nt = 0; nt < 8; nt++)
            s[nt][0] = s[nt][1] = s[nt][2] = s[nt][3] = 0.f;

        #pragma unroll
        for (int kst = 0; kst < 4; kst++) {
            const int koff = ((2 * kst + hi) ^ sw) << 4;
            uint32_t af[4], bf[4][4];
            ldsm4(af, aqbase + koff);
            #pragma unroll
            for (int p = 0; p < 4; p++) ldsm4(bf[p], kbB + p * 2048 + koff);
            #pragma unroll
            for (int nt = 0; nt < 8; nt++)
                mma16h(s[nt], af, bf[nt >> 1][nt & 1], bf[nt >> 1][(nt & 1) + 2]);
        }

        float mx0 = -1e30f, mx1 = -1e30f;
        #pragma unroll
        for (int nt = 0; nt < 8; nt++) {
            mx0 = fmaxf(mx0, fmaxf(s[nt][0], s[nt][1]));
            mx1 = fmaxf(mx1, fmaxf(s[nt][2], s[nt][3]));
        }
        mx0 = fmaxf(mx0, __shfl_xor_sync(0xffffffffu, mx0, 1));
        mx0 = fmaxf(mx0, __shfl_xor_sync(0xffffffffu, mx0, 2));
        mx1 = fmaxf(mx1, __shfl_xor_sync(0xffffffffu, mx1, 1));
        mx1 = fmaxf(mx1, __shfl_xor_sync(0xffffffffu, mx1, 2));
        float mn0 = fmaxf(m0, mx0), mn1 = fmaxf(m1, mx1);
        float c0 = __expf(m0 - mn0), c1 = __expf(m1 - mn1);
        float p0 = 0.f, p1 = 0.f;
        #pragma unroll
        for (int nt = 0; nt < 8; nt++) {
            s[nt][0] = __expf(s[nt][0] - mn0);
            s[nt][1] = __expf(s[nt][1] - mn0);
            s[nt][2] = __expf(s[nt][2] - mn1);
            s[nt][3] = __expf(s[nt][3] - mn1);
            p0 += s[nt][0] + s[nt][1];
            p1 += s[nt][2] + s[nt][3];
        }
        p0 += __shfl_xor_sync(0xffffffffu, p0, 1);
        p0 += __shfl_xor_sync(0xffffffffu, p0, 2);
        p1 += __shfl_xor_sync(0xffffffffu, p1, 1);
        p1 += __shfl_xor_sync(0xffffffffu, p1, 2);
        l0 = l0 * c0 + p0; l1 = l1 * c1 + p1;
        m0 = mn0; m1 = mn1;
        #pragma unroll
        for (int nt = 0; nt < 8; nt++) {
            o[nt][0] *= c0; o[nt][1] *= c0;
            o[nt][2] *= c1; o[nt][3] *= c1;
        }

        #pragma unroll
        for (int nt = 0; nt < 8; nt++) {
            *(__half2*)(psw + g * 64 + ((nt ^ g) << 3) + 2 * cq) =
                __floats2half2_rn(s[nt][0], s[nt][1]);
            *(__half2*)(psw + (g + 8) * 64 + ((nt ^ g) << 3) + 2 * cq) =
                __floats2half2_rn(s[nt][2], s[nt][3]);
        }
        __syncwarp();

        #pragma unroll
        for (int kst = 0; kst < 4; kst++) {
            const int koff = ((2 * kst + hi) ^ sw) << 4;
            uint32_t ap[4];
            ldsm4(ap, apbase + koff);
            #pragma unroll
            for (int nt2 = 0; nt2 < 4; nt2++) {
                const int voff = ((nt2 * 2 + hi) ^ sw) << 4;
                uint32_t tv[4];
                ldsm4t(tv, vbB + kst * 2048 + voff);
                mma16h(o[2 * nt2],     ap, tv[0], tv[1]);
                mma16h(o[2 * nt2 + 1], ap, tv[2], tv[3]);
            }
        }
    }

    const int b = bh >> 4;
    const float i0 = 1.f / l0, i1 = 1.f / l1;
    const int n0 = qbase + w * 16 + g;
    const size_t base0 = ((size_t)(b * SEQ_N + n0)) * DHID + h * DHEAD;
    const size_t base1 = ((size_t)(b * SEQ_N + n0 + 8)) * DHID + h * DHEAD;
    #pragma unroll
    for (int nt = 0; nt < 8; nt++) {
        int col = nt * 8 + 2 * cq;
        *(__half2*)&h_ao[base0 + col] = __floats2half2_rn(o[nt][0] * i0, o[nt][1] * i0);
        *(__half2*)&h_ao[base1 + col] = __floats2half2_rn(o[nt][2] * i1, o[nt][3] * i1);
    }
}

// ---------------- launch ----------------
extern "C" void kernel_launch(void* const* d_in, const int* in_sizes, int n_in,
                              void* d_out, int out_size)
{
    const float* x      = (const float*)d_in[0];
    const float* ctx    = (const float*)d_in[1];
    const float* skv    = (const float*)d_in[2];
    const float* sq     = (const float*)d_in[3];
    const float* gamma  = (const float*)d_in[4];
    const float* nullkv = (const float*)d_in[5];
    const float* Wq     = (const float*)d_in[6];
    const float* Wkv    = (const float*)d_in[7];
    const float* Wo     = (const float*)d_in[8];
    float* out = (float*)d_out;

    static int smem_set = 0;
    if (!smem_set) {
        cudaFuncSetAttribute(attn_fp16, cudaFuncAttributeMaxDynamicSharedMemorySize,
                             AT_SMEM);
        cudaFuncSetAttribute(gemm_qkv, cudaFuncAttributeMaxDynamicSharedMemorySize,
                             GH_SMEM);
        cudaFuncSetAttribute(gemm_o, cudaFuncAttributeMaxDynamicSharedMemorySize,
                             GH_SMEM);
        smem_set = 1;
    }

    prep_weights_kernel<<<(W_TOTAL_N4 + 255) / 256, 256>>>(
        (const float4*)Wq, (const float4*)Wkv, (const float4*)Wo);

    rmsnorm_kernel<<<BATCH * SEQ_N + BATCH * ROUTES * SEQ_K, 256>>>(x, ctx, gamma);

    // merged Q + KV projection: 384 CTAs
    gemm_qkv<<<384, 256, GH_SMEM>>>(sq, skv);

    attn_fp16<<<dim3(SEQ_N / 128, BATCH * NHEAD), 256, AT_SMEM>>>(nullkv);

    // O projection: 4096 x 2048 x 1024
    gemm_o<<<dim3(DIMF / 256, (BATCH * SEQ_N) / 128), 256, GH_SMEM>>>(out);
}

// round 9
// speedup vs baseline: 7.6878x; 1.0389x over previous
#include <cuda_runtime.h>
#include <cuda_fp16.h>
#include <math.h>
#include <stdint.h>

#define BATCH 4
#define SEQ_N 1024
#define SEQ_K 1024
#define DIMF  2048
#define NHEAD 16
#define DHEAD 64
#define ROUTES 2
#define HPR   (NHEAD/ROUTES)
#define DHID  (NHEAD*DHEAD)   // 1024

// ---------------- scratch (static device allocations) ----------------
__device__ __half h_xn[(size_t)BATCH*SEQ_N*DIMF];          // normed x (fp16)
__device__ __half h_cn[(size_t)BATCH*ROUTES*SEQ_K*DIMF];   // normed context (fp16)
__device__ __half h_q [(size_t)BATCH*NHEAD*SEQ_N*DHEAD];   // fp16, scaled score_q/8
__device__ __half h_k [(size_t)BATCH*NHEAD*SEQ_K*DHEAD];   // fp16, scaled score_kv
__device__ __half h_v [(size_t)BATCH*NHEAD*SEQ_K*DHEAD];   // fp16, scaled score_kv
__device__ __half h_ao[(size_t)BATCH*SEQ_N*DHID];          // attn out (fp16)
__device__ __half h_wq [(size_t)DHID*DIMF];                // fp16 weights
__device__ __half h_wkv[(size_t)2*DHID*DIMF];
__device__ __half h_wo [(size_t)DIMF*DHID];

// ---------------- helpers ----------------
__device__ __forceinline__ void cp16(void* dst_smem, const void* src) {
    uint32_t d = (uint32_t)__cvta_generic_to_shared(dst_smem);
    asm volatile("cp.async.cg.shared.global [%0], [%1], 16;" :: "r"(d), "l"(src));
}
__device__ __forceinline__ void mma16h(float* c, const uint32_t* a, uint32_t b0, uint32_t b1) {
    asm volatile("mma.sync.aligned.m16n8k16.row.col.f32.f16.f16.f32 "
        "{%0,%1,%2,%3},{%4,%5,%6,%7},{%8,%9},{%0,%1,%2,%3};"
        : "+f"(c[0]), "+f"(c[1]), "+f"(c[2]), "+f"(c[3])
        : "r"(a[0]), "r"(a[1]), "r"(a[2]), "r"(a[3]), "r"(b0), "r"(b1));
}
__device__ __forceinline__ void ldsm4(uint32_t* r, uint32_t addr) {
    asm volatile("ldmatrix.sync.aligned.m8n8.x4.shared.b16 {%0,%1,%2,%3}, [%4];"
        : "=r"(r[0]), "=r"(r[1]), "=r"(r[2]), "=r"(r[3]) : "r"(addr));
}
__device__ __forceinline__ void ldsm4t(uint32_t* r, uint32_t addr) {
    asm volatile("ldmatrix.sync.aligned.m8n8.x4.trans.shared.b16 {%0,%1,%2,%3}, [%4];"
        : "=r"(r[0]), "=r"(r[1]), "=r"(r[2]), "=r"(r[3]) : "r"(addr));
}
__device__ __forceinline__ uint32_t s2u(const void* p) {
    uint32_t a;
    asm("{ .reg .u64 t; cvta.to.shared.u64 t, %1; cvt.u32.u64 %0, t; }"
        : "=r"(a) : "l"(p));
    return a;
}
__device__ __forceinline__ uint32_t packh2(float a, float b) {
    __half2 h = __floats2half2_rn(a, b);
    return *(uint32_t*)&h;
}

// ---------------- merged prep: rmsnorm rows + weight conversion ----------------
#define WQ_N4  ((DHID * DIMF) / 4)            // 524288
#define WKV_N4 ((2 * DHID * DIMF) / 4)        // 1048576
#define WO_N4  ((DIMF * DHID) / 4)            // 524288
#define W_TOTAL_N4 (WQ_N4 + WKV_N4 + WO_N4)
#define NORM_ROWS (BATCH * SEQ_N + BATCH * ROUTES * SEQ_K)   // 12288
#define WBLOCKS   ((W_TOTAL_N4 + 255) / 256)                 // 8192

__global__ void __launch_bounds__(256) prep_kernel(
    const float* __restrict__ x, const float* __restrict__ ctx,
    const float* __restrict__ gamma,
    const float4* __restrict__ Wq, const float4* __restrict__ Wkv,
    const float4* __restrict__ Wo)
{
    const int blk = blockIdx.x;
    const int t = threadIdx.x;

    if (blk >= NORM_ROWS) {
        int i = (blk - NORM_ROWS) * 256 + t;
        if (i >= W_TOTAL_N4) return;
        const float4* src;
        __half2* dst;
        int j = i;
        if (j < WQ_N4)                  { src = Wq;  dst = (__half2*)h_wq; }
        else if ((j -= WQ_N4) < WKV_N4) { src = Wkv; dst = (__half2*)h_wkv; }
        else { j -= WKV_N4;               src = Wo;  dst = (__half2*)h_wo; }
        float4 v = src[j];
        dst[2 * j]     = __floats2half2_rn(v.x, v.y);
        dst[2 * j + 1] = __floats2half2_rn(v.z, v.w);
        return;
    }

    const long row = blk;
    const float* in;
    __half* out;
    if (row < BATCH * SEQ_N) {
        in  = x + row * (long)DIMF;
        out = h_xn + row * (long)DIMF;
    } else {
        long r = row - BATCH * SEQ_N;
        in  = ctx + r * (long)DIMF;
        out = h_cn + r * (long)DIMF;
    }
    const float4* xr = (const float4*)in;
    const float4* g4 = (const float4*)gamma;

    float4 v0 = xr[2 * t];
    float4 v1 = xr[2 * t + 1];
    float ss = v0.x*v0.x + v0.y*v0.y + v0.z*v0.z + v0.w*v0.w
             + v1.x*v1.x + v1.y*v1.y + v1.z*v1.z + v1.w*v1.w;
    #pragma unroll
    for (int o = 16; o; o >>= 1) ss += __shfl_xor_sync(0xffffffffu, ss, o);
    __shared__ float red[8];
    if ((t & 31) == 0) red[t >> 5] = ss;
    __syncthreads();
    float tot = 0.f;
    #pragma unroll
    for (int i = 0; i < 8; i++) tot += red[i];
    const float s = sqrtf((float)DIMF) / fmaxf(sqrtf(tot), 1e-12f);

    float4 ga = g4[2 * t], gb = g4[2 * t + 1];
    uint4 pk;
    pk.x = packh2(v0.x*s*ga.x, v0.y*s*ga.y);
    pk.y = packh2(v0.z*s*ga.z, v0.w*s*ga.w);
    pk.z = packh2(v1.x*s*gb.x, v1.y*s*gb.y);
    pk.w = packh2(v1.z*s*gb.z, v1.w*s*gb.w);
    ((uint4*)out)[t] = pk;
}

// ---------------- fp16 tensor-core GEMM core ----------------
#define GH_STAGE 49152
#define GH_SMEM  (3 * GH_STAGE)

// ---- merged Q + KV projection (K = 2048) ----
__global__ void __launch_bounds__(256, 1) gemm_qkv(
    const float* __restrict__ sq, const float* __restrict__ skv)
{
    constexpr int K  = DIMF;
    constexpr int NC = K / 64;

    extern __shared__ char smem[];
    const uint32_t smu = s2u(smem);

    const int id = blockIdx.x;
    const bool isQ = (id < 128);
    int bm, bn, bz = 0;
    const __half *A, *Bp;
    if (isQ) {
        bm = id >> 2; bn = id & 3;
        A  = h_xn + (size_t)bm * 128 * K;
        Bp = h_wq + (size_t)bn * 256 * K;
    } else {
        int r = id - 128;
        bz = r >> 5;
        int rr = r & 31;
        bm = rr >> 2; bn = rr & 3;
        A  = h_cn + ((size_t)bz * SEQ_K + (size_t)bm * 128) * K;
        Bp = h_wkv + (size_t)(bz & 1) * DHID * K + (size_t)bn * 256 * K;
    }

    const int tid = threadIdx.x;
    const int lane = tid & 31, warp = tid >> 5;
    const int wm = warp >> 2, wn = warp & 3;
    const int g = lane >> 2, cq = lane & 3;

    const int lr = tid >> 3, lg = tid & 7;
    const int lsw = (lg ^ (lr & 7)) << 4;
    auto load_chunk = [&](int c, int st) {
        char* aB = smem + st * GH_STAGE;
        char* bB = aB + 16384;
        const size_t ko = (size_t)c * 64 + lg * 8;
        #pragma unroll
        for (int t4 = 0; t4 < 4; t4++)
            cp16(aB + (lr + t4 * 32) * 128 + lsw, A + (size_t)(lr + t4 * 32) * K + ko);
        #pragma unroll
        for (int t4 = 0; t4 < 8; t4++)
            cp16(bB + (lr + t4 * 32) * 128 + lsw, Bp + (size_t)(lr + t4 * 32) * K + ko);
    };

    const int lrow = lane & 15, hi = lane >> 4;
    const int sw = lane & 7;
    int moff[4], noff[4];
    #pragma unroll
    for (int mt = 0; mt < 4; mt++) moff[mt] = (wm * 64 + mt * 16 + lrow) * 128;
    #pragma unroll
    for (int p = 0; p < 4; p++)    noff[p]  = (wn * 64 + p * 16 + lrow) * 128 + 16384;

    float c[4][8][4];
    #pragma unroll
    for (int mt = 0; mt < 4; mt++)
        #pragma unroll
        for (int nt = 0; nt < 8; nt++)
            #pragma unroll
            for (int i = 0; i < 4; i++) c[mt][nt][i] = 0.f;

    load_chunk(0, 0);
    asm volatile("cp.async.commit_group;");
    load_chunk(1, 1);
    asm volatile("cp.async.commit_group;");

    #pragma unroll 1
    for (int t = 0; t < NC; t++) {
        asm volatile("cp.async.wait_group 1;");
        __syncthreads();

        if (t + 2 < NC) load_chunk(t + 2, (t + 2) % 3);
        asm volatile("cp.async.commit_group;");

        const uint32_t sb = smu + (t % 3) * GH_STAGE;

        #pragma unroll
        for (int ks = 0; ks < 4; ks++) {
            const int koff = ((2 * ks + hi) ^ sw) << 4;
            uint32_t af[4][4], bf[4][4];
            #pragma unroll
            for (int mt = 0; mt < 4; mt++) ldsm4(af[mt], sb + moff[mt] + koff);
            #pragma unroll
            for (int p = 0; p < 4; p++)    ldsm4(bf[p], sb + noff[p] + koff);
            #pragma unroll
            for (int mt = 0; mt < 4; mt++)
                #pragma unroll
                for (int nt = 0; nt < 8; nt++)
                    mma16h(c[mt][nt], af[mt], bf[nt >> 1][nt & 1], bf[nt >> 1][(nt & 1) + 2]);
        }
    }

    // ---- epilogue ----
    #pragma unroll
    for (int mt = 0; mt < 4; mt++) {
        #pragma unroll
        for (int i = 0; i < 2; i++) {
            const int m = bm * 128 + wm * 64 + mt * 16 + g + i * 8;
            const float srow = isQ ? sq[m] * 0.125f : skv[(size_t)bz * SEQ_K + m];
            #pragma unroll
            for (int nt = 0; nt < 8; nt++) {
                const int o = bn * 256 + wn * 64 + (nt >> 1) * 16 + (nt & 1) * 8 + 2 * cq;
                float v0 = c[mt][nt][i * 2 + 0];
                float v1 = c[mt][nt][i * 2 + 1];
                __half2 hv = __floats2half2_rn(v0 * srow, v1 * srow);
                if (isQ) {
                    int b = m >> 10, nn = m & 1023;
                    int h = o >> 6,  d  = o & 63;
                    *(__half2*)&h_q[(((size_t)(b * NHEAD + h)) * SEQ_N + nn) * DHEAD + d] = hv;
                } else {
                    int hp = o >> 7, dd = o & 127;
                    int b = bz >> 1, rt = bz & 1;
                    size_t base = (((size_t)(b * NHEAD + rt * HPR + hp)) * SEQ_K + m) * DHEAD;
                    if (dd < DHEAD) *(__half2*)&h_k[base + dd]         = hv;
                    else            *(__half2*)&h_v[base + dd - DHEAD] = hv;
                }
            }
        }
    }
}

// ---- O projection (K = 1024) ----
__global__ void __launch_bounds__(256, 1) gemm_o(float* __restrict__ out)
{
    constexpr int K  = DHID;
    constexpr int NC = K / 64;

    extern __shared__ char smem[];
    const uint32_t smu = s2u(smem);

    const int bm = blockIdx.y, bn = blockIdx.x;
    const int tid = threadIdx.x;
    const int lane = tid & 31, warp = tid >> 5;
    const int wm = warp >> 2, wn = warp & 3;
    const int g = lane >> 2, cq = lane & 3;

    const __half* A  = h_ao + (size_t)bm * 128 * K;
    const __half* Bp = h_wo + (size_t)bn * 256 * K;

    const int lr = tid >> 3, lg = tid & 7;
    const int lsw = (lg ^ (lr & 7)) << 4;
    auto load_chunk = [&](int c, int st) {
        char* aB = smem + st * GH_STAGE;
        char* bB = aB + 16384;
        const size_t ko = (size_t)c * 64 + lg * 8;
        #pragma unroll
        for (int t4 = 0; t4 < 4; t4++)
            cp16(aB + (lr + t4 * 32) * 128 + lsw, A + (size_t)(lr + t4 * 32) * K + ko);
        #pragma unroll
        for (int t4 = 0; t4 < 8; t4++)
            cp16(bB + (lr + t4 * 32) * 128 + lsw, Bp + (size_t)(lr + t4 * 32) * K + ko);
    };

    const int lrow = lane & 15, hi = lane >> 4;
    const int sw = lane & 7;
    int moff[4], noff[4];
    #pragma unroll
    for (int mt = 0; mt < 4; mt++) moff[mt] = (wm * 64 + mt * 16 + lrow) * 128;
    #pragma unroll
    for (int p = 0; p < 4; p++)    noff[p]  = (wn * 64 + p * 16 + lrow) * 128 + 16384;

    float c[4][8][4];
    #pragma unroll
    for (int mt = 0; mt < 4; mt++)
        #pragma unroll
        for (int nt = 0; nt < 8; nt++)
            #pragma unroll
            for (int i = 0; i < 4; i++) c[mt][nt][i] = 0.f;

    load_chunk(0, 0);
    asm volatile("cp.async.commit_group;");
    load_chunk(1, 1);
    asm volatile("cp.async.commit_group;");

    #pragma unroll 1
    for (int t = 0; t < NC; t++) {
        asm volatile("cp.async.wait_group 1;");
        __syncthreads();

        if (t + 2 < NC) load_chunk(t + 2, (t + 2) % 3);
        asm volatile("cp.async.commit_group;");

        const uint32_t sb = smu + (t % 3) * GH_STAGE;

        #pragma unroll
        for (int ks = 0; ks < 4; ks++) {
            const int koff = ((2 * ks + hi) ^ sw) << 4;
            uint32_t af[4][4], bf[4][4];
            #pragma unroll
            for (int mt = 0; mt < 4; mt++) ldsm4(af[mt], sb + moff[mt] + koff);
            #pragma unroll
            for (int p = 0; p < 4; p++)    ldsm4(bf[p], sb + noff[p] + koff);
            #pragma unroll
            for (int mt = 0; mt < 4; mt++)
                #pragma unroll
                for (int nt = 0; nt < 8; nt++)
                    mma16h(c[mt][nt], af[mt], bf[nt >> 1][nt & 1], bf[nt >> 1][(nt & 1) + 2]);
        }
    }

    #pragma unroll
    for (int mt = 0; mt < 4; mt++) {
        #pragma unroll
        for (int i = 0; i < 2; i++) {
            const int m = bm * 128 + wm * 64 + mt * 16 + g + i * 8;
            #pragma unroll
            for (int nt = 0; nt < 8; nt++) {
                const int o = bn * 256 + wn * 64 + (nt >> 1) * 16 + (nt & 1) * 8 + 2 * cq;
                *(float2*)&out[(size_t)m * DIMF + o] =
                    make_float2(c[mt][nt][i * 2 + 0], c[mt][nt][i * 2 + 1]);
            }
        }
    }
}

// ---------------- fp16 flash attention, P kept in registers ----------------
// smem layout (bytes): qs [128][64]h @0 (16384), ks 2x[64][64]h @16384 (16384),
//                      vs 2x[64][64]h @32768 (16384), nk/nv float[64] @49152.
#define AT_SMEM 49664

__global__ void __launch_bounds__(256, 2) attn_fp16(const float* __restrict__ nullkv)
{
    extern __shared__ __half sh[];
    __half* qs = sh;                   // halves 0..8192
    __half* ks = sh + 8192;            // halves 8192..16384  (2 bufs x 4096)
    __half* vs = sh + 16384;           // halves 16384..24576 (2 bufs x 4096)
    float* nk = (float*)(sh + 24576);  // byte 49152
    float* nv = nk + 64;
    const uint32_t smu = s2u(sh);

    const int bh = blockIdx.y, h = bh & (NHEAD - 1);
    const int qbase = blockIdx.x * 128;
    const int tid = threadIdx.x, lane = tid & 31, w = tid >> 5;
    const int g = lane >> 2, cq = lane & 3;
    const int lrow = lane & 15, hi = lane >> 4;
    const int sw = lane & 7;

    const __half* qg = h_q + ((size_t)bh * SEQ_N + qbase) * DHEAD;
    const __half* kgp = h_k + (size_t)bh * SEQ_K * DHEAD;
    const __half* vgp = h_v + (size_t)bh * SEQ_K * DHEAD;

    #pragma unroll
    for (int i = 0; i < 4; i++) {
        int idx = tid + i * 256;
        int r = idx >> 3, gg = idx & 7;
        cp16(qs + r * 64 + ((gg ^ (r & 7)) << 3), qg + (size_t)r * DHEAD + gg * 8);
    }
    if (tid < 64)       nk[tid]      = nullkv[h * DHEAD + tid];
    else if (tid < 128) nv[tid - 64] = nullkv[NHEAD * DHEAD + h * DHEAD + (tid - 64)];

    auto load_kv = [&](int tile, int buf) {
        const __half* kt = kgp + (size_t)tile * 64 * DHEAD;
        const __half* vt = vgp + (size_t)tile * 64 * DHEAD;
        __half* kd = ks + buf * 4096;
        __half* vd = vs + buf * 4096;
        #pragma unroll
        for (int i = 0; i < 2; i++) {
            int idx = tid + i * 256;
            int r = idx >> 3, gg = idx & 7;
            int off = r * 64 + ((gg ^ (r & 7)) << 3);
            cp16(kd + off, kt + (size_t)r * DHEAD + gg * 8);
            cp16(vd + off, vt + (size_t)r * DHEAD + gg * 8);
        }
    };
    load_kv(0, 0);
    asm volatile("cp.async.commit_group;");

    asm volatile("cp.async.wait_group 0;");
    __syncthreads();

    // null-key init
    float m0, m1, l0 = 1.f, l1 = 1.f;
    {
        int row = w * 16 + lrow;
        int halfo = hi * 32;
        float s = 0.f;
        #pragma unroll
        for (int d = 0; d < 32; d++) {
            int cidx = halfo + d;
            int gg = cidx >> 3;
            float qv = __half2float(qs[row * 64 + ((gg ^ (row & 7)) << 3) + (cidx & 7)]);
            s += qv * nk[cidx];
        }
        s += __shfl_xor_sync(0xffffffffu, s, 16);
        m0 = __shfl_sync(0xffffffffu, s, g);
        m1 = __shfl_sync(0xffffffffu, s, g + 8);
    }
    float o[8][4];
    #pragma unroll
    for (int nt = 0; nt < 8; nt++) {
        float va = nv[nt * 8 + 2 * cq], vb = nv[nt * 8 + 2 * cq + 1];
        o[nt][0] = va; o[nt][1] = vb; o[nt][2] = va; o[nt][3] = vb;
    }

    const uint32_t aqbase = smu + (w * 16 + lrow) * 128;

    #pragma unroll 1
    for (int t = 0; t < 16; t++) {
        if (t > 0) {
            asm volatile("cp.async.wait_group 0;");
            __syncthreads();
        }
        if (t + 1 < 16) load_kv(t + 1, (t + 1) & 1);
        asm volatile("cp.async.commit_group;");

        const uint32_t kbB = smu + 16384 + (t & 1) * 8192 + lrow * 128;
        const uint32_t vbB = smu + 32768 + (t & 1) * 8192 + lrow * 128;

        // S = Q K^T
        float s[8][4];
        #pragma unroll
        for (int nt = 0; nt < 8; nt++)
            s[nt][0] = s[nt][1] = s[nt][2] = s[nt][3] = 0.f;

        #pragma unroll
        for (int kst = 0; kst < 4; kst++) {
            const int koff = ((2 * kst + hi) ^ sw) << 4;
            uint32_t af[4], bf[4][4];
            ldsm4(af, aqbase + koff);
            #pragma unroll
            for (int p = 0; p < 4; p++) ldsm4(bf[p], kbB + p * 2048 + koff);
            #pragma unroll
            for (int nt = 0; nt < 8; nt++)
                mma16h(s[nt], af, bf[nt >> 1][nt & 1], bf[nt >> 1][(nt & 1) + 2]);
        }

        // online softmax
        float mx0 = -1e30f, mx1 = -1e30f;
        #pragma unroll
        for (int nt = 0; nt < 8; nt++) {
            mx0 = fmaxf(mx0, fmaxf(s[nt][0], s[nt][1]));
            mx1 = fmaxf(mx1, fmaxf(s[nt][2], s[nt][3]));
        }
        mx0 = fmaxf(mx0, __shfl_xor_sync(0xffffffffu, mx0, 1));
        mx0 = fmaxf(mx0, __shfl_xor_sync(0xffffffffu, mx0, 2));
        mx1 = fmaxf(mx1, __shfl_xor_sync(0xffffffffu, mx1, 1));
        mx1 = fmaxf(mx1, __shfl_xor_sync(0xffffffffu, mx1, 2));
        float mn0 = fmaxf(m0, mx0), mn1 = fmaxf(m1, mx1);
        float c0 = __expf(m0 - mn0), c1 = __expf(m1 - mn1);
        float p0 = 0.f, p1 = 0.f;
        #pragma unroll
        for (int nt = 0; nt < 8; nt++) {
            s[nt][0] = __expf(s[nt][0] - mn0);
            s[nt][1] = __expf(s[nt][1] - mn0);
            s[nt][2] = __expf(s[nt][2] - mn1);
            s[nt][3] = __expf(s[nt][3] - mn1);
            p0 += s[nt][0] + s[nt][1];
            p1 += s[nt][2] + s[nt][3];
        }
        p0 += __shfl_xor_sync(0xffffffffu, p0, 1);
        p0 += __shfl_xor_sync(0xffffffffu, p0, 2);
        p1 += __shfl_xor_sync(0xffffffffu, p1, 1);
        p1 += __shfl_xor_sync(0xffffffffu, p1, 2);
        l0 = l0 * c0 + p0; l1 = l1 * c1 + p1;
        m0 = mn0; m1 = mn1;
        #pragma unroll
        for (int nt = 0; nt < 8; nt++) {
            o[nt][0] *= c0; o[nt][1] *= c0;
            o[nt][2] *= c1; o[nt][3] *= c1;
        }

        // O += P V : P built directly from S fragments (identity remap).
        #pragma unroll
        for (int kc = 0; kc < 4; kc++) {
            uint32_t ap[4];
            ap[0] = packh2(s[2 * kc][0],     s[2 * kc][1]);
            ap[1] = packh2(s[2 * kc][2],     s[2 * kc][3]);
            ap[2] = packh2(s[2 * kc + 1][0], s[2 * kc + 1][1]);
            ap[3] = packh2(s[2 * kc + 1][2], s[2 * kc + 1][3]);
            #pragma unroll
            for (int nt2 = 0; nt2 < 4; nt2++) {
                const int voff = ((nt2 * 2 + hi) ^ sw) << 4;
                uint32_t tv[4];
                ldsm4t(tv, vbB + kc * 2048 + voff);
                mma16h(o[2 * nt2],     ap, tv[0], tv[1]);
                mma16h(o[2 * nt2 + 1], ap, tv[2], tv[3]);
            }
        }
    }

    const int b = bh >> 4;
    const float i0 = 1.f / l0, i1 = 1.f / l1;
    const int n0 = qbase + w * 16 + g;
    const size_t base0 = ((size_t)(b * SEQ_N + n0)) * DHID + h * DHEAD;
    const size_t base1 = ((size_t)(b * SEQ_N + n0 + 8)) * DHID + h * DHEAD;
    #pragma unroll
    for (int nt = 0; nt < 8; nt++) {
        int col = nt * 8 + 2 * cq;
        *(__half2*)&h_ao[base0 + col] = __floats2half2_rn(o[nt][0] * i0, o[nt][1] * i0);
        *(__half2*)&h_ao[base1 + col] = __floats2half2_rn(o[nt][2] * i1, o[nt][3] * i1);
    }
}

// ---------------- launch ----------------
extern "C" void kernel_launch(void* const* d_in, const int* in_sizes, int n_in,
                              void* d_out, int out_size)
{
    const float* x      = (const float*)d_in[0];
    const float* ctx    = (const float*)d_in[1];
    const float* skv    = (const float*)d_in[2];
    const float* sq     = (const float*)d_in[3];
    const float* gamma  = (const float*)d_in[4];
    const float* nullkv = (const float*)d_in[5];
    const float* Wq     = (const float*)d_in[6];
    const float* Wkv    = (const float*)d_in[7];
    const float* Wo     = (const float*)d_in[8];
    float* out = (float*)d_out;

    static int smem_set = 0;
    if (!smem_set) {
        cudaFuncSetAttribute(attn_fp16, cudaFuncAttributeMaxDynamicSharedMemorySize,
                             AT_SMEM);
        cudaFuncSetAttribute(gemm_qkv, cudaFuncAttributeMaxDynamicSharedMemorySize,
                             GH_SMEM);
        cudaFuncSetAttribute(gemm_o, cudaFuncAttributeMaxDynamicSharedMemorySize,
                             GH_SMEM);
        smem_set = 1;
    }

    prep_kernel<<<NORM_ROWS + WBLOCKS, 256>>>(
        x, ctx, gamma, (const float4*)Wq, (const float4*)Wkv, (const float4*)Wo);

    gemm_qkv<<<384, 256, GH_SMEM>>>(sq, skv);

    attn_fp16<<<dim3(SEQ_N / 128, BATCH * NHEAD), 256, AT_SMEM>>>(nullkv);

    gemm_o<<<dim3(DIMF / 256, (BATCH * SEQ_N) / 128), 256, GH_SMEM>>>(out);
}

// round 11
// speedup vs baseline: 7.8357x; 1.0192x over previous
#include <cuda_runtime.h>
#include <cuda_fp16.h>
#include <math.h>
#include <stdint.h>

#define BATCH 4
#define SEQ_N 1024
#define SEQ_K 1024
#define DIMF  2048
#define NHEAD 16
#define DHEAD 64
#define ROUTES 2
#define HPR   (NHEAD/ROUTES)
#define DHID  (NHEAD*DHEAD)   // 1024

// ---------------- scratch (static device allocations) ----------------
__device__ __half h_xn[(size_t)BATCH*SEQ_N*DIMF];
__device__ __half h_cn[(size_t)BATCH*ROUTES*SEQ_K*DIMF];
__device__ __half h_q [(size_t)BATCH*NHEAD*SEQ_N*DHEAD];
__device__ __half h_k [(size_t)BATCH*NHEAD*SEQ_K*DHEAD];
__device__ __half h_v [(size_t)BATCH*NHEAD*SEQ_K*DHEAD];
__device__ __half h_ao[(size_t)BATCH*SEQ_N*DHID];
__device__ __half h_wq [(size_t)DHID*DIMF];
__device__ __half h_wkv[(size_t)2*DHID*DIMF];
__device__ __half h_wo [(size_t)DIMF*DHID];

// ---------------- helpers ----------------
__device__ __forceinline__ void cp16(void* dst_smem, const void* src) {
    uint32_t d = (uint32_t)__cvta_generic_to_shared(dst_smem);
    asm volatile("cp.async.cg.shared.global [%0], [%1], 16;" :: "r"(d), "l"(src));
}
__device__ __forceinline__ void mma16h(float* c, const uint32_t* a, uint32_t b0, uint32_t b1) {
    asm volatile("mma.sync.aligned.m16n8k16.row.col.f32.f16.f16.f32 "
        "{%0,%1,%2,%3},{%4,%5,%6,%7},{%8,%9},{%0,%1,%2,%3};"
        : "+f"(c[0]), "+f"(c[1]), "+f"(c[2]), "+f"(c[3])
        : "r"(a[0]), "r"(a[1]), "r"(a[2]), "r"(a[3]), "r"(b0), "r"(b1));
}
__device__ __forceinline__ void ldsm4(uint32_t* r, uint32_t addr) {
    asm volatile("ldmatrix.sync.aligned.m8n8.x4.shared.b16 {%0,%1,%2,%3}, [%4];"
        : "=r"(r[0]), "=r"(r[1]), "=r"(r[2]), "=r"(r[3]) : "r"(addr));
}
__device__ __forceinline__ void ldsm4t(uint32_t* r, uint32_t addr) {
    asm volatile("ldmatrix.sync.aligned.m8n8.x4.trans.shared.b16 {%0,%1,%2,%3}, [%4];"
        : "=r"(r[0]), "=r"(r[1]), "=r"(r[2]), "=r"(r[3]) : "r"(addr));
}
__device__ __forceinline__ uint32_t s2u(const void* p) {
    uint32_t a;
    asm("{ .reg .u64 t; cvta.to.shared.u64 t, %1; cvt.u32.u64 %0, t; }"
        : "=r"(a) : "l"(p));
    return a;
}
__device__ __forceinline__ uint32_t packh2(float a, float b) {
    __half2 h = __floats2half2_rn(a, b);
    return *(uint32_t*)&h;
}

// ---------------- merged prep: rmsnorm rows + weight conversion ----------------
#define WQ_N4  ((DHID * DIMF) / 4)
#define WKV_N4 ((2 * DHID * DIMF) / 4)
#define WO_N4  ((DIMF * DHID) / 4)
#define W_TOTAL_N4 (WQ_N4 + WKV_N4 + WO_N4)
#define NORM_ROWS (BATCH * SEQ_N + BATCH * ROUTES * SEQ_K)   // 12288
#define WBLOCKS   ((W_TOTAL_N4 + 255) / 256)                 // 8192

__global__ void __launch_bounds__(256) prep_kernel(
    const float* __restrict__ x, const float* __restrict__ ctx,
    const float* __restrict__ gamma,
    const float4* __restrict__ Wq, const float4* __restrict__ Wkv,
    const float4* __restrict__ Wo)
{
    const int blk = blockIdx.x;
    const int t = threadIdx.x;

    if (blk >= NORM_ROWS) {
        int i = (blk - NORM_ROWS) * 256 + t;
        if (i >= W_TOTAL_N4) return;
        const float4* src;
        __half2* dst;
        int j = i;
        if (j < WQ_N4)                  { src = Wq;  dst = (__half2*)h_wq; }
        else if ((j -= WQ_N4) < WKV_N4) { src = Wkv; dst = (__half2*)h_wkv; }
        else { j -= WKV_N4;               src = Wo;  dst = (__half2*)h_wo; }
        float4 v = src[j];
        dst[2 * j]     = __floats2half2_rn(v.x, v.y);
        dst[2 * j + 1] = __floats2half2_rn(v.z, v.w);
        return;
    }

    const long row = blk;
    const float* in;
    __half* out;
    if (row < BATCH * SEQ_N) {
        in  = x + row * (long)DIMF;
        out = h_xn + row * (long)DIMF;
    } else {
        long r = row - BATCH * SEQ_N;
        in  = ctx + r * (long)DIMF;
        out = h_cn + r * (long)DIMF;
    }
    const float4* xr = (const float4*)in;
    const float4* g4 = (const float4*)gamma;

    float4 v0 = xr[2 * t];
    float4 v1 = xr[2 * t + 1];
    float ss = v0.x*v0.x + v0.y*v0.y + v0.z*v0.z + v0.w*v0.w
             + v1.x*v1.x + v1.y*v1.y + v1.z*v1.z + v1.w*v1.w;
    #pragma unroll
    for (int o = 16; o; o >>= 1) ss += __shfl_xor_sync(0xffffffffu, ss, o);
    __shared__ float red[8];
    if ((t & 31) == 0) red[t >> 5] = ss;
    __syncthreads();
    float tot = 0.f;
    #pragma unroll
    for (int i = 0; i < 8; i++) tot += red[i];
    const float s = sqrtf((float)DIMF) / fmaxf(sqrtf(tot), 1e-12f);

    float4 ga = g4[2 * t], gb = g4[2 * t + 1];
    uint4 pk;
    pk.x = packh2(v0.x*s*ga.x, v0.y*s*ga.y);
    pk.y = packh2(v0.z*s*ga.z, v0.w*s*ga.w);
    pk.z = packh2(v1.x*s*gb.x, v1.y*s*gb.y);
    pk.w = packh2(v1.z*s*gb.z, v1.w*s*gb.w);
    ((uint4*)out)[t] = pk;
}

// ---------------- fp16 tensor-core GEMM core ----------------
// CTA tile 128x128, BK=64 halves (128B rows), 3-stage cp.async (96KB smem),
// 256 threads (8 warps 2x4), warp tile 64x32, TWO CTAs per SM (reg cap 128).
// swizzle: 16B group g of row r stored at group (g ^ (r&7)).
#define GH_STAGE 32768
#define GH_SMEM  (3 * GH_STAGE)

// ---- merged Q + KV projection (K = 2048) ----
// grid.x = 768: blocks [0,256) -> Q tiles (bm 32 x bn 8);
//               [256,768) -> KV tiles (bz 8 x bm 8 x bn 8).
__global__ void __launch_bounds__(256, 2) gemm_qkv(
    const float* __restrict__ sq, const float* __restrict__ skv)
{
    constexpr int K  = DIMF;
    constexpr int NC = K / 64;

    extern __shared__ char smem[];
    const uint32_t smu = s2u(smem);

    const int id = blockIdx.x;
    const bool isQ = (id < 256);
    int bm, bn, bz = 0;
    const __half *A, *Bp;
    if (isQ) {
        bm = id >> 3; bn = id & 7;
        A  = h_xn + (size_t)bm * 128 * K;
        Bp = h_wq + (size_t)bn * 128 * K;
    } else {
        int r = id - 256;
        bz = r >> 6;
        int rr = r & 63;
        bm = rr >> 3; bn = rr & 7;
        A  = h_cn + ((size_t)bz * SEQ_K + (size_t)bm * 128) * K;
        Bp = h_wkv + (size_t)(bz & 1) * DHID * K + (size_t)bn * 128 * K;
    }

    const int tid = threadIdx.x;
    const int lane = tid & 31, warp = tid >> 5;
    const int wm = warp >> 2, wn = warp & 3;
    const int g = lane >> 2, cq = lane & 3;

    const int lr = tid >> 3, lg = tid & 7;
    const int lsw = (lg ^ (lr & 7)) << 4;
    auto load_chunk = [&](int c, int st) {
        char* aB = smem + st * GH_STAGE;
        char* bB = aB + 16384;
        const size_t ko = (size_t)c * 64 + lg * 8;
        #pragma unroll
        for (int t4 = 0; t4 < 4; t4++)
            cp16(aB + (lr + t4 * 32) * 128 + lsw, A + (size_t)(lr + t4 * 32) * K + ko);
        #pragma unroll
        for (int t4 = 0; t4 < 4; t4++)
            cp16(bB + (lr + t4 * 32) * 128 + lsw, Bp + (size_t)(lr + t4 * 32) * K + ko);
    };

    const int lrow = lane & 15, hi = lane >> 4;
    const int sw = lane & 7;
    int moff[4], noff[2];
    #pragma unroll
    for (int mt = 0; mt < 4; mt++) moff[mt] = (wm * 64 + mt * 16 + lrow) * 128;
    #pragma unroll
    for (int p = 0; p < 2; p++)    noff[p]  = (wn * 32 + p * 16 + lrow) * 128 + 16384;

    float c[4][4][4];
    #pragma unroll
    for (int mt = 0; mt < 4; mt++)
        #pragma unroll
        for (int nt = 0; nt < 4; nt++)
            #pragma unroll
            for (int i = 0; i < 4; i++) c[mt][nt][i] = 0.f;

    load_chunk(0, 0);
    asm volatile("cp.async.commit_group;");
    load_chunk(1, 1);
    asm volatile("cp.async.commit_group;");

    #pragma unroll 1
    for (int t = 0; t < NC; t++) {
        asm volatile("cp.async.wait_group 1;");
        __syncthreads();

        if (t + 2 < NC) load_chunk(t + 2, (t + 2) % 3);
        asm volatile("cp.async.commit_group;");

        const uint32_t sb = smu + (t % 3) * GH_STAGE;

        #pragma unroll
        for (int ks = 0; ks < 4; ks++) {
            const int koff = ((2 * ks + hi) ^ sw) << 4;
            uint32_t af[4][4], bf[2][4];
            #pragma unroll
            for (int mt = 0; mt < 4; mt++) ldsm4(af[mt], sb + moff[mt] + koff);
            #pragma unroll
            for (int p = 0; p < 2; p++)    ldsm4(bf[p], sb + noff[p] + koff);
            #pragma unroll
            for (int mt = 0; mt < 4; mt++)
                #pragma unroll
                for (int nt = 0; nt < 4; nt++)
                    mma16h(c[mt][nt], af[mt], bf[nt >> 1][nt & 1], bf[nt >> 1][(nt & 1) + 2]);
        }
    }

    // ---- epilogue ----
    #pragma unroll
    for (int mt = 0; mt < 4; mt++) {
        #pragma unroll
        for (int i = 0; i < 2; i++) {
            const int m = bm * 128 + wm * 64 + mt * 16 + g + i * 8;
            const float srow = isQ ? sq[m] * 0.125f : skv[(size_t)bz * SEQ_K + m];
            #pragma unroll
            for (int nt = 0; nt < 4; nt++) {
                const int o = bn * 128 + wn * 32 + (nt >> 1) * 16 + (nt & 1) * 8 + 2 * cq;
                float v0 = c[mt][nt][i * 2 + 0];
                float v1 = c[mt][nt][i * 2 + 1];
                __half2 hv = __floats2half2_rn(v0 * srow, v1 * srow);
                if (isQ) {
                    int b = m >> 10, nn = m & 1023;
                    int h = o >> 6,  d  = o & 63;
                    *(__half2*)&h_q[(((size_t)(b * NHEAD + h)) * SEQ_N + nn) * DHEAD + d] = hv;
                } else {
                    int hp = o >> 7, dd = o & 127;
                    int b = bz >> 1, rt = bz & 1;
                    size_t base = (((size_t)(b * NHEAD + rt * HPR + hp)) * SEQ_K + m) * DHEAD;
                    if (dd < DHEAD) *(__half2*)&h_k[base + dd]         = hv;
                    else            *(__half2*)&h_v[base + dd - DHEAD] = hv;
                }
            }
        }
    }
}

// ---- O projection (K = 1024), same 128x128 / 2-CTA structure ----
__global__ void __launch_bounds__(256, 2) gemm_o(float* __restrict__ out)
{
    constexpr int K  = DHID;
    constexpr int NC = K / 64;

    extern __shared__ char smem[];
    const uint32_t smu = s2u(smem);

    const int bm = blockIdx.y, bn = blockIdx.x;
    const int tid = threadIdx.x;
    const int lane = tid & 31, warp = tid >> 5;
    const int wm = warp >> 2, wn = warp & 3;
    const int g = lane >> 2, cq = lane & 3;

    const __half* A  = h_ao + (size_t)bm * 128 * K;
    const __half* Bp = h_wo + (size_t)bn * 128 * K;

    const int lr = tid >> 3, lg = tid & 7;
    const int lsw = (lg ^ (lr & 7)) << 4;
    auto load_chunk = [&](int c, int st) {
        char* aB = smem + st * GH_STAGE;
        char* bB = aB + 16384;
        const size_t ko = (size_t)c * 64 + lg * 8;
        #pragma unroll
        for (int t4 = 0; t4 < 4; t4++)
            cp16(aB + (lr + t4 * 32) * 128 + lsw, A + (size_t)(lr + t4 * 32) * K + ko);
        #pragma unroll
        for (int t4 = 0; t4 < 4; t4++)
            cp16(bB + (lr + t4 * 32) * 128 + lsw, Bp + (size_t)(lr + t4 * 32) * K + ko);
    };

    const int lrow = lane & 15, hi = lane >> 4;
    const int sw = lane & 7;
    int moff[4], noff[2];
    #pragma unroll
    for (int mt = 0; mt < 4; mt++) moff[mt] = (wm * 64 + mt * 16 + lrow) * 128;
    #pragma unroll
    for (int p = 0; p < 2; p++)    noff[p]  = (wn * 32 + p * 16 + lrow) * 128 + 16384;

    float c[4][4][4];
    #pragma unroll
    for (int mt = 0; mt < 4; mt++)
        #pragma unroll
        for (int nt = 0; nt < 4; nt++)
            #pragma unroll
            for (int i = 0; i < 4; i++) c[mt][nt][i] = 0.f;

    load_chunk(0, 0);
    asm volatile("cp.async.commit_group;");
    load_chunk(1, 1);
    asm volatile("cp.async.commit_group;");

    #pragma unroll 1
    for (int t = 0; t < NC; t++) {
        asm volatile("cp.async.wait_group 1;");
        __syncthreads();

        if (t + 2 < NC) load_chunk(t + 2, (t + 2) % 3);
        asm volatile("cp.async.commit_group;");

        const uint32_t sb = smu + (t % 3) * GH_STAGE;

        #pragma unroll
        for (int ks = 0; ks < 4; ks++) {
            const int koff = ((2 * ks + hi) ^ sw) << 4;
            uint32_t af[4][4], bf[2][4];
            #pragma unroll
            for (int mt = 0; mt < 4; mt++) ldsm4(af[mt], sb + moff[mt] + koff);
            #pragma unroll
            for (int p = 0; p < 2; p++)    ldsm4(bf[p], sb + noff[p] + koff);
            #pragma unroll
            for (int mt = 0; mt < 4; mt++)
                #pragma unroll
                for (int nt = 0; nt < 4; nt++)
                    mma16h(c[mt][nt], af[mt], bf[nt >> 1][nt & 1], bf[nt >> 1][(nt & 1) + 2]);
        }
    }

    #pragma unroll
    for (int mt = 0; mt < 4; mt++) {
        #pragma unroll
        for (int i = 0; i < 2; i++) {
            const int m = bm * 128 + wm * 64 + mt * 16 + g + i * 8;
            #pragma unroll
            for (int nt = 0; nt < 4; nt++) {
                const int o = bn * 128 + wn * 32 + (nt >> 1) * 16 + (nt & 1) * 8 + 2 * cq;
                *(float2*)&out[(size_t)m * DIMF + o] =
                    make_float2(c[mt][nt][i * 2 + 0], c[mt][nt][i * 2 + 1]);
            }
        }
    }
}

// ---------------- fp16 flash attention, P kept in registers ----------------
// smem (bytes): qs [128][64]h @0 (16384), ks 2x[64][64]h @16384,
//               vs 2x[64][64]h @32768, nk/nv float[64] @49152.
#define AT_SMEM 49664

__global__ void __launch_bounds__(256, 2) attn_fp16(const float* __restrict__ nullkv)
{
    extern __shared__ __half sh[];
    __half* qs = sh;
    __half* ks = sh + 8192;
    __half* vs = sh + 16384;
    float* nk = (float*)(sh + 24576);
    float* nv = nk + 64;
    const uint32_t smu = s2u(sh);

    const int bh = blockIdx.y, h = bh & (NHEAD - 1);
    const int qbase = blockIdx.x * 128;
    const int tid = threadIdx.x, lane = tid & 31, w = tid >> 5;
    const int g = lane >> 2, cq = lane & 3;
    const int lrow = lane & 15, hi = lane >> 4;
    const int sw = lane & 7;

    const __half* qg = h_q + ((size_t)bh * SEQ_N + qbase) * DHEAD;
    const __half* kgp = h_k + (size_t)bh * SEQ_K * DHEAD;
    const __half* vgp = h_v + (size_t)bh * SEQ_K * DHEAD;

    #pragma unroll
    for (int i = 0; i < 4; i++) {
        int idx = tid + i * 256;
        int r = idx >> 3, gg = idx & 7;
        cp16(qs + r * 64 + ((gg ^ (r & 7)) << 3), qg + (size_t)r * DHEAD + gg * 8);
    }
    if (tid < 64)       nk[tid]      = nullkv[h * DHEAD + tid];
    else if (tid < 128) nv[tid - 64] = nullkv[NHEAD * DHEAD + h * DHEAD + (tid - 64)];

    auto load_kv = [&](int tile, int buf) {
        const __half* kt = kgp + (size_t)tile * 64 * DHEAD;
        const __half* vt = vgp + (size_t)tile * 64 * DHEAD;
        __half* kd = ks + buf * 4096;
        __half* vd = vs + buf * 4096;
        #pragma unroll
        for (int i = 0; i < 2; i++) {
            int idx = tid + i * 256;
            int r = idx >> 3, gg = idx & 7;
            int off = r * 64 + ((gg ^ (r & 7)) << 3);
            cp16(kd + off, kt + (size_t)r * DHEAD + gg * 8);
            cp16(vd + off, vt + (size_t)r * DHEAD + gg * 8);
        }
    };
    load_kv(0, 0);
    asm volatile("cp.async.commit_group;");

    asm volatile("cp.async.wait_group 0;");
    __syncthreads();

    float m0, m1, l0 = 1.f, l1 = 1.f;
    {
        int row = w * 16 + lrow;
        int halfo = hi * 32;
        float s = 0.f;
        #pragma unroll
        for (int d = 0; d < 32; d++) {
            int cidx = halfo + d;
            int gg = cidx >> 3;
            float qv = __half2float(qs[row * 64 + ((gg ^ (row & 7)) << 3) + (cidx & 7)]);
            s += qv * nk[cidx];
        }
        s += __shfl_xor_sync(0xffffffffu, s, 16);
        m0 = __shfl_sync(0xffffffffu, s, g);
        m1 = __shfl_sync(0xffffffffu, s, g + 8);
    }
    float o[8][4];
    #pragma unroll
    for (int nt = 0; nt < 8; nt++) {
        float va = nv[nt * 8 + 2 * cq], vb = nv[nt * 8 + 2 * cq + 1];
        o[nt][0] = va; o[nt][1] = vb; o[nt][2] = va; o[nt][3] = vb;
    }

    const uint32_t aqbase = smu + (w * 16 + lrow) * 128;

    #pragma unroll 1
    for (int t = 0; t < 16; t++) {
        if (t > 0) {
            asm volatile("cp.async.wait_group 0;");
            __syncthreads();
        }
        if (t + 1 < 16) load_kv(t + 1, (t + 1) & 1);
        asm volatile("cp.async.commit_group;");

        const uint32_t kbB = smu + 16384 + (t & 1) * 8192 + lrow * 128;
        const uint32_t vbB = smu + 32768 + (t & 1) * 8192 + lrow * 128;

        float s[8][4];
        #pragma unroll
        for (int nt = 0; nt < 8; nt++)
            s[nt][0] = s[nt][1] = s[nt][2] = s[nt][3] = 0.f;

        #pragma unroll
        for (int kst = 0; kst < 4; kst++) {
            const int koff = ((2 * kst + hi) ^ sw) << 4;
            uint32_t af[4], bf[4][4];
            ldsm4(af, aqbase + koff);
            #pragma unroll
            for (int p = 0; p < 4; p++) ldsm4(bf[p], kbB + p * 2048 + koff);
            #pragma unroll
            for (int nt = 0; nt < 8; nt++)
                mma16h(s[nt], af, bf[nt >> 1][nt & 1], bf[nt >> 1][(nt & 1) + 2]);
        }

        float mx0 = -1e30f, mx1 = -1e30f;
        #pragma unroll
        for (int nt = 0; nt < 8; nt++) {
            mx0 = fmaxf(mx0, fmaxf(s[nt][0], s[nt][1]));
            mx1 = fmaxf(mx1, fmaxf(s[nt][2], s[nt][3]));
        }
        mx0 = fmaxf(mx0, __shfl_xor_sync(0xffffffffu, mx0, 1));
        mx0 = fmaxf(mx0, __shfl_xor_sync(0xffffffffu, mx0, 2));
        mx1 = fmaxf(mx1, __shfl_xor_sync(0xffffffffu, mx1, 1));
        mx1 = fmaxf(mx1, __shfl_xor_sync(0xffffffffu, mx1, 2));
        float mn0 = fmaxf(m0, mx0), mn1 = fmaxf(m1, mx1);
        float c0 = __expf(m0 - mn0), c1 = __expf(m1 - mn1);
        float p0 = 0.f, p1 = 0.f;
        #pragma unroll
        for (int nt = 0; nt < 8; nt++) {
            s[nt][0] = __expf(s[nt][0] - mn0);
            s[nt][1] = __expf(s[nt][1] - mn0);
            s[nt][2] = __expf(s[nt][2] - mn1);
            s[nt][3] = __expf(s[nt][3] - mn1);
            p0 += s[nt][0] + s[nt][1];
            p1 += s[nt][2] + s[nt][3];
        }
        p0 += __shfl_xor_sync(0xffffffffu, p0, 1);
        p0 += __shfl_xor_sync(0xffffffffu, p0, 2);
        p1 += __shfl_xor_sync(0xffffffffu, p1, 1);
        p1 += __shfl_xor_sync(0xffffffffu, p1, 2);
        l0 = l0 * c0 + p0; l1 = l1 * c1 + p1;
        m0 = mn0; m1 = mn1;
        #pragma unroll
        for (int nt = 0; nt < 8; nt++) {
            o[nt][0] *= c0; o[nt][1] *= c0;
            o[nt][2] *= c1; o[nt][3] *= c1;
        }

        #pragma unroll
        for (int kc = 0; kc < 4; kc++) {
            uint32_t ap[4];
            ap[0] = packh2(s[2 * kc][0],     s[2 * kc][1]);
            ap[1] = packh2(s[2 * kc][2],     s[2 * kc][3]);
            ap[2] = packh2(s[2 * kc + 1][0], s[2 * kc + 1][1]);
            ap[3] = packh2(s[2 * kc + 1][2], s[2 * kc + 1][3]);
            #pragma unroll
            for (int nt2 = 0; nt2 < 4; nt2++) {
                const int voff = ((nt2 * 2 + hi) ^ sw) << 4;
                uint32_t tv[4];
                ldsm4t(tv, vbB + kc * 2048 + voff);
                mma16h(o[2 * nt2],     ap, tv[0], tv[1]);
                mma16h(o[2 * nt2 + 1], ap, tv[2], tv[3]);
            }
        }
    }

    const int b = bh >> 4;
    const float i0 = 1.f / l0, i1 = 1.f / l1;
    const int n0 = qbase + w * 16 + g;
    const size_t base0 = ((size_t)(b * SEQ_N + n0)) * DHID + h * DHEAD;
    const size_t base1 = ((size_t)(b * SEQ_N + n0 + 8)) * DHID + h * DHEAD;
    #pragma unroll
    for (int nt = 0; nt < 8; nt++) {
        int col = nt * 8 + 2 * cq;
        *(__half2*)&h_ao[base0 + col] = __floats2half2_rn(o[nt][0] * i0, o[nt][1] * i0);
        *(__half2*)&h_ao[base1 + col] = __floats2half2_rn(o[nt][2] * i1, o[nt][3] * i1);
    }
}

// ---------------- launch ----------------
extern "C" void kernel_launch(void* const* d_in, const int* in_sizes, int n_in,
                              void* d_out, int out_size)
{
    const float* x      = (const float*)d_in[0];
    const float* ctx    = (const float*)d_in[1];
    const float* skv    = (const float*)d_in[2];
    const float* sq     = (const float*)d_in[3];
    const float* gamma  = (const float*)d_in[4];
    const float* nullkv = (const float*)d_in[5];
    const float* Wq     = (const float*)d_in[6];
    const float* Wkv    = (const float*)d_in[7];
    const float* Wo     = (const float*)d_in[8];
    float* out = (float*)d_out;

    static int smem_set = 0;
    if (!smem_set) {
        cudaFuncSetAttribute(attn_fp16, cudaFuncAttributeMaxDynamicSharedMemorySize,
                             AT_SMEM);
        cudaFuncSetAttribute(gemm_qkv, cudaFuncAttributeMaxDynamicSharedMemorySize,
                             GH_SMEM);
        cudaFuncSetAttribute(gemm_o, cudaFuncAttributeMaxDynamicSharedMemorySize,
                             GH_SMEM);
        smem_set = 1;
    }

    prep_kernel<<<NORM_ROWS + WBLOCKS, 256>>>(
        x, ctx, gamma, (const float4*)Wq, (const float4*)Wkv, (const float4*)Wo);

    // merged Q + KV projection: 768 CTAs (128x128 tiles, 2 CTAs/SM)
    gemm_qkv<<<768, 256, GH_SMEM>>>(sq, skv);

    attn_fp16<<<dim3(SEQ_N / 128, BATCH * NHEAD), 256, AT_SMEM>>>(nullkv);

    // O projection: 4096 x 2048 x 1024, 512 CTAs
    gemm_o<<<dim3(DIMF / 128, (BATCH * SEQ_N) / 128), 256, GH_SMEM>>>(out);
}